// round 4
// baseline (speedup 1.0000x reference)
#include <cuda_runtime.h>
#include <cuda_bf16.h>
#include <math.h>
#include <cstdint>

#define D1 512
#define D2 1024
#define NS 16
#define MTOT 16384
#define LMASK 4095

// ---------------- scratch (static device globals; no allocation) ----------------
__device__ float g_t0v[(size_t)MTOT * D2];
__device__ float g_t1v[(size_t)MTOT * D2];
__device__ float g_t2v[(size_t)MTOT * D2];
__device__ float g_cb[MTOT];
// activation limbs + per-row scales
__device__ int8_t g_xnQh[(size_t)MTOT * D1], g_xnQl[(size_t)MTOT * D1];
__device__ int8_t g_q0h[(size_t)MTOT * D2], g_q0l[(size_t)MTOT * D2];
__device__ int8_t g_q1h[(size_t)MTOT * D2], g_q1l[(size_t)MTOT * D2];
__device__ int8_t g_q2h[(size_t)MTOT * D2], g_q2l[(size_t)MTOT * D2];
__device__ float g_sXn[MTOT], g_s0[MTOT], g_s1[MTOT], g_s2[MTOT];
// weight limbs [koff][Cout][Cin] + per-col scale / inv-scale
__device__ int8_t g_wInpH[3 * D1 * D2], g_wInpL[3 * D1 * D2];
__device__ int8_t g_wCnvH[3 * D2 * D2], g_wCnvL[3 * D2 * D2];
__device__ int8_t g_wClH[3 * D2 * D2],  g_wClL[3 * D2 * D2];
__device__ int8_t g_wF1H[3 * D2 * D2],  g_wF1L[3 * D2 * D2];
__device__ int8_t g_wResH[3 * D1 * D2], g_wResL[3 * D1 * D2];
__device__ int8_t g_wOutH[3 * D2 * D1], g_wOutL[3 * D2 * D1];
__device__ float g_swInp[D2], g_swiInp[D2];
__device__ float g_swCnv[D2], g_swiCnv[D2];
__device__ float g_swCl[D2],  g_swiCl[D2];
__device__ float g_swF1[D2],  g_swiF1[D2];
__device__ float g_swRes[D2], g_swiRes[D2];
__device__ float g_swOut[D1], g_swiOut[D1];

// ---------------- small math ----------------
__device__ __forceinline__ float softplus_f(float x) {
    return (x > 20.0f) ? x : log1pf(expf(x));
}
__device__ __forceinline__ float swish_f(float x) {
    return x / (1.0f + expf(-x));
}
__device__ __forceinline__ int quant16(float v, float inv) {
    int q = __float2int_rn(v * inv);
    q = max(-32512, min(32512, q));
    return q;
}

// ---------------- ptx helpers ----------------
__device__ __forceinline__ uint32_t s2u(const void* p) {
    uint32_t a;
    asm("{ .reg .u64 t; cvta.to.shared.u64 t, %1; cvt.u32.u64 %0, t; }"
        : "=r"(a) : "l"(p));
    return a;
}
__device__ __forceinline__ void cp16(uint32_t saddr, const void* gaddr, uint32_t sz) {
    asm volatile("cp.async.ca.shared.global [%0], [%1], 16, %2;"
                 :: "r"(saddr), "l"(gaddr), "r"(sz) : "memory");
}
__device__ __forceinline__ void cp_commit() {
    asm volatile("cp.async.commit_group;" ::: "memory");
}
template <int N>
__device__ __forceinline__ void cp_wait() {
    asm volatile("cp.async.wait_group %0;" :: "n"(N) : "memory");
}
__device__ __forceinline__ void ldsm4(uint32_t* r, uint32_t addr) {
    asm volatile("ldmatrix.sync.aligned.m8n8.x4.shared.b16 {%0,%1,%2,%3}, [%4];"
                 : "=r"(r[0]), "=r"(r[1]), "=r"(r[2]), "=r"(r[3]) : "r"(addr));
}
__device__ __forceinline__ void imma16832(int* d, const uint32_t* a,
                                          const uint32_t* b) {
    asm volatile(
        "mma.sync.aligned.m16n8k32.row.col.s32.s8.s8.s32 "
        "{%0,%1,%2,%3}, {%4,%5,%6,%7}, {%8,%9}, {%0,%1,%2,%3};"
        : "+r"(d[0]), "+r"(d[1]), "+r"(d[2]), "+r"(d[3])
        : "r"(a[0]), "r"(a[1]), "r"(a[2]), "r"(a[3]), "r"(b[0]), "r"(b[1]));
}

// ---------------- rmsnorm -> int16 limbs ----------------
__global__ void rmsnorm_q(const float* __restrict__ x,
                          const float* __restrict__ w,
                          int8_t* __restrict__ qh, int8_t* __restrict__ ql,
                          float* __restrict__ S) {
    int row = blockIdx.x;
    int t = threadIdx.x;  // 128 threads * float4
    const float4* xr = (const float4*)(x + (size_t)row * D1);
    float4 xv = xr[t];
    float ss = xv.x * xv.x + xv.y * xv.y + xv.z * xv.z + xv.w * xv.w;
#pragma unroll
    for (int off = 16; off; off >>= 1) ss += __shfl_xor_sync(0xffffffffu, ss, off);
    __shared__ float sred[4];
    __shared__ float samax[4];
    if ((t & 31) == 0) sred[t >> 5] = ss;
    __syncthreads();
    float tot = sred[0] + sred[1] + sred[2] + sred[3];
    float s = rsqrtf(tot * (1.0f / (float)D1) + 1e-5f);
    float4 wv = ((const float4*)w)[t];
    float o[4];
    o[0] = xv.x * s * wv.x; o[1] = xv.y * s * wv.y;
    o[2] = xv.z * s * wv.z; o[3] = xv.w * s * wv.w;
    float am = fmaxf(fmaxf(fabsf(o[0]), fabsf(o[1])),
                     fmaxf(fabsf(o[2]), fabsf(o[3])));
#pragma unroll
    for (int off = 16; off; off >>= 1)
        am = fmaxf(am, __shfl_xor_sync(0xffffffffu, am, off));
    if ((t & 31) == 0) samax[t >> 5] = am;
    __syncthreads();
    am = fmaxf(fmaxf(samax[0], samax[1]), fmaxf(samax[2], samax[3]));
    float inv = (am > 1e-30f) ? 32512.0f / am : 0.0f;
    float sc = (am > 1e-30f) ? am / 32512.0f : 0.0f;
    char hq[4], lq[4];
#pragma unroll
    for (int j = 0; j < 4; j++) {
        int q = quant16(o[j], inv);
        int ah = (q + 128) >> 8;
        hq[j] = (char)ah;
        lq[j] = (char)(q - (ah << 8));
    }
    size_t base = (size_t)row * (D1 / 4) + t;
    ((char4*)qh)[base] = make_char4(hq[0], hq[1], hq[2], hq[3]);
    ((char4*)ql)[base] = make_char4(lq[0], lq[1], lq[2], lq[3]);
    if (t == 0) S[row] = sc;
}

// ---------------- activation quantizer (C = 1024) ----------------
__global__ void qact(const float* __restrict__ X, int8_t* __restrict__ qh,
                     int8_t* __restrict__ ql, float* __restrict__ S, int M) {
    int warp = (int)((blockIdx.x * blockDim.x + threadIdx.x) >> 5);
    int lane = threadIdx.x & 31;
    if (warp >= M) return;
    const float4* xr = (const float4*)(X + (size_t)warp * D2);
    float4 v[8];
    float am = 0.f;
#pragma unroll
    for (int i = 0; i < 8; i++) {
        v[i] = xr[i * 32 + lane];
        am = fmaxf(am, fmaxf(fmaxf(fabsf(v[i].x), fabsf(v[i].y)),
                             fmaxf(fabsf(v[i].z), fabsf(v[i].w))));
    }
#pragma unroll
    for (int off = 16; off; off >>= 1)
        am = fmaxf(am, __shfl_xor_sync(0xffffffffu, am, off));
    float inv = (am > 1e-30f) ? 32512.0f / am : 0.0f;
    float sc = (am > 1e-30f) ? am / 32512.0f : 0.0f;
    size_t base = (size_t)warp * (D2 / 4);
#pragma unroll
    for (int i = 0; i < 8; i++) {
        float o[4] = {v[i].x, v[i].y, v[i].z, v[i].w};
        char hq[4], lq[4];
#pragma unroll
        for (int j = 0; j < 4; j++) {
            int q = quant16(o[j], inv);
            int ah = (q + 128) >> 8;
            hq[j] = (char)ah;
            lq[j] = (char)(q - (ah << 8));
        }
        ((char4*)qh)[base + i * 32 + lane] = make_char4(hq[0], hq[1], hq[2], hq[3]);
        ((char4*)ql)[base + i * 32 + lane] = make_char4(lq[0], lq[1], lq[2], lq[3]);
    }
    if (lane == 0) S[warp] = sc;
}

// ---------------- weight per-col amax ----------------
__global__ void wcolmax(const float* __restrict__ W, float* __restrict__ Sw,
                        float* __restrict__ SwInv, int Cin, int Cout) {
    int n = blockIdx.x * blockDim.x + threadIdx.x;
    if (n >= Cout) return;
    float am = 0.f;
    for (int r = 0; r < 3 * Cin; r++) am = fmaxf(am, fabsf(W[(size_t)r * Cout + n]));
    Sw[n] = (am > 1e-30f) ? am / 32512.0f : 0.0f;
    SwInv[n] = (am > 1e-30f) ? 32512.0f / am : 0.0f;
}

// ---------------- weight transpose + quantize: W[k][Cin][Cout] -> T[k][Cout][Cin] ----------------
__global__ void wtq(const float* __restrict__ W, const float* __restrict__ SwInv,
                    int8_t* __restrict__ Th, int8_t* __restrict__ Tl,
                    int Cin, int Cout) {
    __shared__ float tile[32][33];
    int koff = blockIdx.z;
    int n0 = blockIdx.x * 32;
    int c0 = blockIdx.y * 32;
    int tx = threadIdx.x, ty = threadIdx.y;  // 32 x 8
    const float* Wk = W + (size_t)koff * Cin * Cout;
#pragma unroll
    for (int r = 0; r < 32; r += 8)
        tile[ty + r][tx] = Wk[(size_t)(c0 + ty + r) * Cout + n0 + tx];
    __syncthreads();
    int8_t* Thk = Th + (size_t)koff * Cout * Cin;
    int8_t* Tlk = Tl + (size_t)koff * Cout * Cin;
#pragma unroll
    for (int r = 0; r < 32; r += 8) {
        int n = n0 + ty + r;
        float v = tile[tx][ty + r];
        int q = quant16(v, SwInv[n]);
        int ah = (q + 128) >> 8;
        Thk[(size_t)n * Cin + c0 + tx] = (int8_t)ah;
        Tlk[(size_t)n * Cin + c0 + tx] = (int8_t)(q - (ah << 8));
    }
}

// ---------------- int8 limb conv-GEMM ----------------
// Y[m,n] = act( sum_{koff,c} X[m+koff-1,c] * WT[koff][n][c] + bias[n] )
// X ~ sA[m]*(256*Xh+Xl), W ~ sB[n]*(256*Wh+Wl); 3 IMMAs per k32 (drop ll).
// CTA tile 128x64, 8 warps (2x4), warp tile 64x16, 3-stage cp.async.
#define ASTR8 80
#define A_TILB (128 * ASTR8)     // 10240
#define B_TILB (64 * ASTR8)      // 5120
#define STG8 (2 * A_TILB + 2 * B_TILB)  // 30720
#define SSCALE_OFF (3 * STG8)    // 92160
#define GEMM_SMEM (SSCALE_OFF + 544)

template <int ACT>
__global__ __launch_bounds__(256, 1) void mm_i8(
    const int8_t* __restrict__ Ah, const int8_t* __restrict__ Al,
    const float* __restrict__ sAr,
    const int8_t* __restrict__ Bh, const int8_t* __restrict__ Bl,
    const float* __restrict__ sBc,
    const float* __restrict__ bias, int Cin, int Cout, int M,
    float* __restrict__ Yv,
    const float* __restrict__ xc, const float* __restrict__ xr,
    const float* __restrict__ cbv) {
    extern __shared__ char smem[];
    const uint32_t sb = s2u(smem);
    float* sS = (float*)(smem + SSCALE_OFF);
    const int tid = threadIdx.x;
    const int wid = tid >> 5;
    const int lane = tid & 31;
    const int warp_m = wid >> 2;   // 0..1
    const int warp_n = wid & 3;    // 0..3
    const int bm = blockIdx.y * 128;
    const int bn = blockIdx.x * 64;
    const int KC = Cin >> 6;
    const int nch = 3 * KC;

    if (tid < 130) {
        int gr = bm - 1 + tid;
        gr = min(max(gr, 0), M - 1);
        sS[tid] = sAr[gr];
    }

    float mst[4][2][4];
    int hh[4][2][4], xx[4][2][4];
#pragma unroll
    for (int i = 0; i < 4; i++)
#pragma unroll
        for (int j = 0; j < 2; j++)
#pragma unroll
            for (int q = 0; q < 4; q++) {
                mst[i][j][q] = 0.f; hh[i][j][q] = 0; xx[i][j][q] = 0;
            }

    const int alr = tid >> 1;
    const int aseg = (tid & 1) * 2;
    const int apos = (bm + alr) & LMASK;
    const int blr = tid >> 2;
    const int bseg = tid & 3;

    auto issue = [&](int cc) {
        int stg = cc % 3;
        int koff = cc / KC;
        int kc = (cc - koff * KC) << 6;
        uint32_t st = sb + (uint32_t)stg * STG8;
        bool av = !((koff == 0 && apos == 0) || (koff == 2 && apos == LMASK));
        uint32_t asz = av ? 16u : 0u;
        long long ar = (long long)(bm + alr) + koff - 1;
        const int8_t* pah = Ah + ar * Cin + kc + aseg * 16;
        const int8_t* pal = Al + ar * Cin + kc + aseg * 16;
        uint32_t sa = st + (uint32_t)alr * ASTR8 + aseg * 16;
        cp16(sa, pah, asz);
        cp16(sa + 16, pah + 16, asz);
        cp16(sa + A_TILB, pal, asz);
        cp16(sa + A_TILB + 16, pal + 16, asz);
        size_t bo = ((size_t)koff * Cout + bn + blr) * Cin + kc + bseg * 16;
        uint32_t sbb = st + 2 * A_TILB + (uint32_t)blr * ASTR8 + bseg * 16;
        cp16(sbb, Bh + bo, 16u);
        cp16(sbb + B_TILB, Bl + bo, 16u);
    };

    issue(0); cp_commit();
    if (nch > 1) { issue(1); cp_commit(); }

    const int arow = warp_m * 64 + (lane & 15);
    const uint32_t akh = (uint32_t)(lane >> 4) * 16;
    const int mi = lane >> 3;
    const int brow = warp_n * 16 + ((mi >> 1) << 3) + (lane & 7);
    const uint32_t bkh = (uint32_t)(mi & 1) * 16;

    for (int cc = 0; cc < nch; cc++) {
        if (cc + 2 < nch) { issue(cc + 2); cp_commit(); cp_wait<2>(); }
        else if (cc + 1 < nch) { cp_wait<1>(); }
        else { cp_wait<0>(); }
        __syncthreads();

        uint32_t st = sb + (uint32_t)(cc % 3) * STG8;
#pragma unroll
        for (int k2 = 0; k2 < 2; k2++) {
            uint32_t ah4[4][4], al4[4][4];
#pragma unroll
            for (int mt = 0; mt < 4; mt++) {
                uint32_t addr = st + (uint32_t)(arow + mt * 16) * ASTR8 +
                                (uint32_t)k2 * 32 + akh;
                ldsm4(ah4[mt], addr);
                ldsm4(al4[mt], addr + A_TILB);
            }
            uint32_t bhf[2][2], blf[2][2];
            {
                uint32_t addr = st + 2 * A_TILB + (uint32_t)brow * ASTR8 +
                                (uint32_t)k2 * 32 + bkh;
                uint32_t t4[4];
                ldsm4(t4, addr);
                bhf[0][0] = t4[0]; bhf[0][1] = t4[1];
                bhf[1][0] = t4[2]; bhf[1][1] = t4[3];
                ldsm4(t4, addr + B_TILB);
                blf[0][0] = t4[0]; blf[0][1] = t4[1];
                blf[1][0] = t4[2]; blf[1][1] = t4[3];
            }
#pragma unroll
            for (int mt = 0; mt < 4; mt++) {
#pragma unroll
                for (int nt = 0; nt < 2; nt++) {
                    imma16832(hh[mt][nt], ah4[mt], bhf[nt]);
                    imma16832(xx[mt][nt], ah4[mt], blf[nt]);
                    imma16832(xx[mt][nt], al4[mt], bhf[nt]);
                }
            }
        }

        // tap boundary: fold int accs into float masters with per-row scale
        if (((cc + 1) % KC) == 0) {
            int koff = cc / KC;
#pragma unroll
            for (int mt = 0; mt < 4; mt++) {
                int l0 = warp_m * 64 + mt * 16 + (lane >> 2) + koff;
                float s0 = sS[l0];
                float s1 = sS[l0 + 8];
#pragma unroll
                for (int nt = 0; nt < 2; nt++) {
#pragma unroll
                    for (int j = 0; j < 2; j++) {
                        mst[mt][nt][j] += s0 * (65536.f * (float)hh[mt][nt][j] +
                                                256.f * (float)xx[mt][nt][j]);
                        mst[mt][nt][2 + j] +=
                            s1 * (65536.f * (float)hh[mt][nt][2 + j] +
                                  256.f * (float)xx[mt][nt][2 + j]);
                        hh[mt][nt][j] = 0; xx[mt][nt][j] = 0;
                        hh[mt][nt][2 + j] = 0; xx[mt][nt][2 + j] = 0;
                    }
                }
            }
        }
        __syncthreads();
    }

    // ---------------- epilogue ----------------
    const int erow = bm + warp_m * 64 + (lane >> 2);
    const int ecol0 = bn + warp_n * 16 + (lane & 3) * 2;
#pragma unroll
    for (int mt = 0; mt < 4; mt++) {
#pragma unroll
        for (int h = 0; h < 2; h++) {
            int row = erow + mt * 16 + h * 8;
            float cbs = 0.f;
            if (ACT == 2) cbs = cbv[row];
            size_t yb = (size_t)row * Cout;
#pragma unroll
            for (int nt = 0; nt < 2; nt++) {
                int col = ecol0 + nt * 8;
                float v0 = mst[mt][nt][2 * h + 0] * sBc[col] + bias[col];
                float v1 = mst[mt][nt][2 * h + 1] * sBc[col + 1] + bias[col + 1];
                if (ACT == 1) { v0 = swish_f(v0); v1 = swish_f(v1); }
                if (ACT == 2) {
                    float2 xcv = *(const float2*)(xc + yb + col);
                    float2 xrv = *(const float2*)(xr + yb + col);
                    v0 = xcv.x * softplus_f(v0) * cbs * xrv.x;
                    v1 = xcv.y * softplus_f(v1) * cbs * xrv.y;
                }
                *(float2*)(Yv + yb + col) = make_float2(v0, v1);
            }
        }
    }
}

// ---------------- fused fc2/fc3 conv + cb scalar (fp32 input) ----------------
__global__ void bc_kernel(const float* __restrict__ X,
                          const float* __restrict__ w2, const float* __restrict__ b2,
                          const float* __restrict__ w3, const float* __restrict__ b3,
                          float* __restrict__ cbout, int M) {
    int warp = (int)((blockIdx.x * blockDim.x + threadIdx.x) >> 5);
    int lane = threadIdx.x & 31;
    if (warp >= M) return;
    float accB[NS], accC[NS];
#pragma unroll
    for (int n = 0; n < NS; n++) { accB[n] = 0.f; accC[n] = 0.f; }
    int pos = warp & LMASK;
    for (int koff = 0; koff < 3; koff++) {
        if ((koff == 0 && pos == 0) || (koff == 2 && pos == LMASK)) continue;
        const float* xrow = X + (size_t)(warp + koff - 1) * D2;
        const float* w2k = w2 + (size_t)koff * D2 * NS;
        const float* w3k = w3 + (size_t)koff * D2 * NS;
        for (int c = lane; c < D2; c += 32) {
            float xv = xrow[c];
            const float4* w2p = (const float4*)(w2k + (size_t)c * NS);
            const float4* w3p = (const float4*)(w3k + (size_t)c * NS);
#pragma unroll
            for (int q = 0; q < 4; q++) {
                float4 wv = w2p[q];
                accB[q * 4 + 0] += xv * wv.x;
                accB[q * 4 + 1] += xv * wv.y;
                accB[q * 4 + 2] += xv * wv.z;
                accB[q * 4 + 3] += xv * wv.w;
                float4 wv3 = w3p[q];
                accC[q * 4 + 0] += xv * wv3.x;
                accC[q * 4 + 1] += xv * wv3.y;
                accC[q * 4 + 2] += xv * wv3.z;
                accC[q * 4 + 3] += xv * wv3.w;
            }
        }
    }
#pragma unroll
    for (int n = 0; n < NS; n++) {
#pragma unroll
        for (int off = 16; off; off >>= 1) {
            accB[n] += __shfl_xor_sync(0xffffffffu, accB[n], off);
            accC[n] += __shfl_xor_sync(0xffffffffu, accC[n], off);
        }
    }
    if (lane == 0) {
        float s = 0.f;
#pragma unroll
        for (int n = 0; n < NS; n++) s += (accB[n] + b2[n]) * (accC[n] + b3[n]);
        cbout[warp] = s;
    }
}

// ---------------- launch ----------------
extern "C" void kernel_launch(void* const* d_in, const int* in_sizes, int n_in,
                              void* d_out, int out_size) {
    const float* x      = (const float*)d_in[0];
    const float* norm_w = (const float*)d_in[1];
    const float* inp_w  = (const float*)d_in[2];
    const float* inp_b  = (const float*)d_in[3];
    const float* conv_w = (const float*)d_in[4];
    const float* conv_b = (const float*)d_in[5];
    const float* cl_w   = (const float*)d_in[6];
    const float* cl_b   = (const float*)d_in[7];
    const float* fc1_w  = (const float*)d_in[8];
    const float* fc1_b  = (const float*)d_in[9];
    const float* fc2_w  = (const float*)d_in[10];
    const float* fc2_b  = (const float*)d_in[11];
    const float* fc3_w  = (const float*)d_in[12];
    const float* fc3_b  = (const float*)d_in[13];
    // d_in[14] = A (mathematically dead)
    const float* res_w  = (const float*)d_in[15];
    const float* res_b  = (const float*)d_in[16];
    const float* out_w  = (const float*)d_in[17];
    const float* out_b  = (const float*)d_in[18];

    int M = in_sizes[0] / D1;  // 16384

    float *t0v, *t1v, *t2v, *cb;
    int8_t *xnQh, *xnQl, *q0h, *q0l, *q1h, *q1l, *q2h, *q2l;
    float *sXn, *s0, *s1, *s2;
    int8_t *wInpH, *wInpL, *wCnvH, *wCnvL, *wClH, *wClL;
    int8_t *wF1H, *wF1L, *wResH, *wResL, *wOutH, *wOutL;
    float *swInp, *swiInp, *swCnv, *swiCnv, *swCl, *swiCl;
    float *swF1, *swiF1, *swRes, *swiRes, *swOut, *swiOut;
    cudaGetSymbolAddress((void**)&t0v, g_t0v);
    cudaGetSymbolAddress((void**)&t1v, g_t1v);
    cudaGetSymbolAddress((void**)&t2v, g_t2v);
    cudaGetSymbolAddress((void**)&cb, g_cb);
    cudaGetSymbolAddress((void**)&xnQh, g_xnQh);
    cudaGetSymbolAddress((void**)&xnQl, g_xnQl);
    cudaGetSymbolAddress((void**)&q0h, g_q0h);
    cudaGetSymbolAddress((void**)&q0l, g_q0l);
    cudaGetSymbolAddress((void**)&q1h, g_q1h);
    cudaGetSymbolAddress((void**)&q1l, g_q1l);
    cudaGetSymbolAddress((void**)&q2h, g_q2h);
    cudaGetSymbolAddress((void**)&q2l, g_q2l);
    cudaGetSymbolAddress((void**)&sXn, g_sXn);
    cudaGetSymbolAddress((void**)&s0, g_s0);
    cudaGetSymbolAddress((void**)&s1, g_s1);
    cudaGetSymbolAddress((void**)&s2, g_s2);
    cudaGetSymbolAddress((void**)&wInpH, g_wInpH);
    cudaGetSymbolAddress((void**)&wInpL, g_wInpL);
    cudaGetSymbolAddress((void**)&wCnvH, g_wCnvH);
    cudaGetSymbolAddress((void**)&wCnvL, g_wCnvL);
    cudaGetSymbolAddress((void**)&wClH, g_wClH);
    cudaGetSymbolAddress((void**)&wClL, g_wClL);
    cudaGetSymbolAddress((void**)&wF1H, g_wF1H);
    cudaGetSymbolAddress((void**)&wF1L, g_wF1L);
    cudaGetSymbolAddress((void**)&wResH, g_wResH);
    cudaGetSymbolAddress((void**)&wResL, g_wResL);
    cudaGetSymbolAddress((void**)&wOutH, g_wOutH);
    cudaGetSymbolAddress((void**)&wOutL, g_wOutL);
    cudaGetSymbolAddress((void**)&swInp, g_swInp);
    cudaGetSymbolAddress((void**)&swiInp, g_swiInp);
    cudaGetSymbolAddress((void**)&swCnv, g_swCnv);
    cudaGetSymbolAddress((void**)&swiCnv, g_swiCnv);
    cudaGetSymbolAddress((void**)&swCl, g_swCl);
    cudaGetSymbolAddress((void**)&swiCl, g_swiCl);
    cudaGetSymbolAddress((void**)&swF1, g_swF1);
    cudaGetSymbolAddress((void**)&swiF1, g_swiF1);
    cudaGetSymbolAddress((void**)&swRes, g_swRes);
    cudaGetSymbolAddress((void**)&swiRes, g_swiRes);
    cudaGetSymbolAddress((void**)&swOut, g_swOut);
    cudaGetSymbolAddress((void**)&swiOut, g_swiOut);

    cudaFuncSetAttribute(mm_i8<0>, cudaFuncAttributeMaxDynamicSharedMemorySize, GEMM_SMEM);
    cudaFuncSetAttribute(mm_i8<1>, cudaFuncAttributeMaxDynamicSharedMemorySize, GEMM_SMEM);
    cudaFuncSetAttribute(mm_i8<2>, cudaFuncAttributeMaxDynamicSharedMemorySize, GEMM_SMEM);

    // ---- weight quantization ----
    wcolmax<<<(D2 + 255) / 256, 256>>>(inp_w, swInp, swiInp, D1, D2);
    wcolmax<<<(D2 + 255) / 256, 256>>>(conv_w, swCnv, swiCnv, D2, D2);
    wcolmax<<<(D2 + 255) / 256, 256>>>(cl_w, swCl, swiCl, D2, D2);
    wcolmax<<<(D2 + 255) / 256, 256>>>(fc1_w, swF1, swiF1, D2, D2);
    wcolmax<<<(D2 + 255) / 256, 256>>>(res_w, swRes, swiRes, D1, D2);
    wcolmax<<<(D1 + 255) / 256, 256>>>(out_w, swOut, swiOut, D2, D1);
    dim3 wblk(32, 8);
    wtq<<<dim3(D2 / 32, D1 / 32, 3), wblk>>>(inp_w, swiInp, wInpH, wInpL, D1, D2);
    wtq<<<dim3(D2 / 32, D2 / 32, 3), wblk>>>(conv_w, swiCnv, wCnvH, wCnvL, D2, D2);
    wtq<<<dim3(D2 / 32, D2 / 32, 3), wblk>>>(cl_w, swiCl, wClH, wClL, D2, D2);
    wtq<<<dim3(D2 / 32, D2 / 32, 3), wblk>>>(fc1_w, swiF1, wF1H, wF1L, D2, D2);
    wtq<<<dim3(D2 / 32, D1 / 32, 3), wblk>>>(res_w, swiRes, wResH, wResL, D1, D2);
    wtq<<<dim3(D1 / 32, D2 / 32, 3), wblk>>>(out_w, swiOut, wOutH, wOutL, D2, D1);

    // 1) xn = rmsnorm(x) -> int16 limbs
    rmsnorm_q<<<M, 128>>>(x, norm_w, xnQh, xnQl, sXn);

    dim3 blk(256);
    dim3 g_big(D2 / 64, M / 128);   // 16 x 128
    dim3 g_out(D1 / 64, M / 128);   // 8 x 128
    int qgrid = (M * 32 + 255) / 256;

    // 2) t0v = conv(xn, inp)
    mm_i8<0><<<g_big, blk, GEMM_SMEM>>>(xnQh, xnQl, sXn, wInpH, wInpL, swInp,
        inp_b, D1, D2, M, t0v, nullptr, nullptr, nullptr);
    qact<<<qgrid, 256>>>(t0v, q0h, q0l, s0, M);
    // 3) t1v = swish(conv(t0, conv))
    mm_i8<1><<<g_big, blk, GEMM_SMEM>>>(q0h, q0l, s0, wCnvH, wCnvL, swCnv,
        conv_b, D2, D2, M, t1v, nullptr, nullptr, nullptr);
    qact<<<qgrid, 256>>>(t1v, q1h, q1l, s1, M);
    // 4) t2v = conv(t1, cl) = x_conv_out
    mm_i8<0><<<g_big, blk, GEMM_SMEM>>>(q1h, q1l, s1, wClH, wClL, swCl,
        cl_b, D2, D2, M, t2v, nullptr, nullptr, nullptr);
    // 5) cb[m] + quantize t2
    bc_kernel<<<qgrid, 256>>>(t2v, fc2_w, fc2_b, fc3_w, fc3_b, cb, M);
    qact<<<qgrid, 256>>>(t2v, q2h, q2l, s2, M);
    // 6) t0v = x_res = swish(conv(xn, res))  (value plane only)
    mm_i8<1><<<g_big, blk, GEMM_SMEM>>>(xnQh, xnQl, sXn, wResH, wResL, swRes,
        res_b, D1, D2, M, t0v, nullptr, nullptr, nullptr);
    // 7) t1v = x_ssm * x_res (s6 epilogue; xc = t2v, xr = t0v)
    mm_i8<2><<<g_big, blk, GEMM_SMEM>>>(q2h, q2l, s2, wF1H, wF1L, swF1,
        fc1_b, D2, D2, M, t1v, t2v, t0v, cb);
    qact<<<qgrid, 256>>>(t1v, q0h, q0l, s0, M);
    // 8) out = conv(t1v, out) -> d_out fp32
    mm_i8<0><<<g_out, blk, GEMM_SMEM>>>(q0h, q0l, s0, wOutH, wOutL, swOut,
        out_b, D2, D1, M, (float*)d_out, nullptr, nullptr, nullptr);
}

// round 5
// speedup vs baseline: 3.0336x; 3.0336x over previous
#include <cuda_runtime.h>
#include <cuda_fp16.h>
#include <math.h>
#include <cstdint>

#define D1 512
#define D2 1024
#define NS 16
#define MTOT 16384
#define LMASK 4095

// ---------------- scratch (static device globals; no allocation) ----------------
__device__ __half g_xnh[(size_t)MTOT * D1], g_xnl[(size_t)MTOT * D1];
__device__ __half g_t0h[(size_t)MTOT * D2], g_t0l[(size_t)MTOT * D2];
__device__ __half g_t1h[(size_t)MTOT * D2], g_t1l[(size_t)MTOT * D2];
__device__ __half g_t2h[(size_t)MTOT * D2], g_t2l[(size_t)MTOT * D2];
__device__ float g_cb[MTOT];
// transposed fp16 weights: [koff][Cout][Cin]
__device__ __half g_wInp[3 * D1 * D2];
__device__ __half g_wCnv[3 * D2 * D2];
__device__ __half g_wCl[3 * D2 * D2];
__device__ __half g_wF1[3 * D2 * D2];
__device__ __half g_wRes[3 * D1 * D2];
__device__ __half g_wOut[3 * D2 * D1];

// ---------------- small math ----------------
__device__ __forceinline__ float softplus_f(float x) {
    return (x > 20.0f) ? x : log1pf(expf(x));
}
__device__ __forceinline__ float swish_f(float x) {
    return x / (1.0f + expf(-x));
}

// ---------------- ptx helpers ----------------
__device__ __forceinline__ uint32_t s2u(const void* p) {
    uint32_t a;
    asm("{ .reg .u64 t; cvta.to.shared.u64 t, %1; cvt.u32.u64 %0, t; }"
        : "=r"(a) : "l"(p));
    return a;
}
__device__ __forceinline__ void cp16(uint32_t saddr, const void* gaddr, uint32_t sz) {
    asm volatile("cp.async.ca.shared.global [%0], [%1], 16, %2;"
                 :: "r"(saddr), "l"(gaddr), "r"(sz) : "memory");
}
__device__ __forceinline__ void cp_commit() {
    asm volatile("cp.async.commit_group;" ::: "memory");
}
template <int N>
__device__ __forceinline__ void cp_wait() {
    asm volatile("cp.async.wait_group %0;" :: "n"(N) : "memory");
}
__device__ __forceinline__ void ldsm4(uint32_t* r, uint32_t addr) {
    asm volatile("ldmatrix.sync.aligned.m8n8.x4.shared.b16 {%0,%1,%2,%3}, [%4];"
                 : "=r"(r[0]), "=r"(r[1]), "=r"(r[2]), "=r"(r[3]) : "r"(addr));
}
__device__ __forceinline__ void hmma(float* d, const uint32_t* a, const uint32_t* b) {
    asm volatile(
        "mma.sync.aligned.m16n8k16.row.col.f32.f16.f16.f32 "
        "{%0,%1,%2,%3}, {%4,%5,%6,%7}, {%8,%9}, {%0,%1,%2,%3};"
        : "+f"(d[0]), "+f"(d[1]), "+f"(d[2]), "+f"(d[3])
        : "r"(a[0]), "r"(a[1]), "r"(a[2]), "r"(a[3]), "r"(b[0]), "r"(b[1]));
}

// ---------------- rmsnorm -> hi/lo fp16 ----------------
__global__ void rmsnorm_h(const float* __restrict__ x,
                          const float* __restrict__ w,
                          __half* __restrict__ yh, __half* __restrict__ yl) {
    int row = blockIdx.x;
    int t = threadIdx.x;  // 128 threads * float4
    const float4* xr = (const float4*)(x + (size_t)row * D1);
    float4 xv = xr[t];
    float ss = xv.x * xv.x + xv.y * xv.y + xv.z * xv.z + xv.w * xv.w;
#pragma unroll
    for (int off = 16; off; off >>= 1) ss += __shfl_xor_sync(0xffffffffu, ss, off);
    __shared__ float sred[4];
    if ((t & 31) == 0) sred[t >> 5] = ss;
    __syncthreads();
    float tot = sred[0] + sred[1] + sred[2] + sred[3];
    float s = rsqrtf(tot * (1.0f / (float)D1) + 1e-5f);
    float4 wv = ((const float4*)w)[t];
    float o[4];
    o[0] = xv.x * s * wv.x; o[1] = xv.y * s * wv.y;
    o[2] = xv.z * s * wv.z; o[3] = xv.w * s * wv.w;
    size_t base = (size_t)row * D1 + t * 4;
#pragma unroll
    for (int j = 0; j < 4; j += 2) {
        __half h0 = __float2half_rn(o[j]);
        __half h1 = __float2half_rn(o[j + 1]);
        __half2 hp; hp.x = h0; hp.y = h1;
        *(__half2*)(yh + base + j) = hp;
        __half2 lp;
        lp.x = __float2half_rn(o[j] - __half2float(h0));
        lp.y = __float2half_rn(o[j + 1] - __half2float(h1));
        *(__half2*)(yl + base + j) = lp;
    }
}

// ---------------- weight transpose + fp16: W[k][Cin][Cout] -> T[k][Cout][Cin] ----------------
__global__ void wtq(const float* __restrict__ W, __half* __restrict__ T,
                    int Cin, int Cout) {
    __shared__ float tile[32][33];
    int koff = blockIdx.z;
    int n0 = blockIdx.x * 32;
    int c0 = blockIdx.y * 32;
    int tx = threadIdx.x, ty = threadIdx.y;  // 32 x 8
    const float* Wk = W + (size_t)koff * Cin * Cout;
#pragma unroll
    for (int r = 0; r < 32; r += 8)
        tile[ty + r][tx] = Wk[(size_t)(c0 + ty + r) * Cout + n0 + tx];
    __syncthreads();
    __half* Tk = T + (size_t)koff * Cout * Cin;
#pragma unroll
    for (int r = 0; r < 32; r += 8)
        Tk[(size_t)(n0 + ty + r) * Cin + c0 + tx] =
            __float2half_rn(tile[tx][ty + r]);
}

// ---------------- fp16 conv-GEMM (mma.sync) ----------------
// Y[m,n] = act( sum_{koff,c} X[m+koff-1,c] * WT[koff][n][c] + bias[n] )
// X = Xh + Xl (fp16 split), W = fp16. 2 HMMAs per k16: ah*w + al*w.
// CTA 128x256, BK=32, warp 64x64 (2x4 warps), 3-stage cp.async, 1 sync/chunk.
#define ASTR 80                 // bytes per smem row (32 halfs + 16B pad)
#define APL (128 * ASTR)        // 10240 per A plane
#define BOFF (2 * APL)          // 20480
#define BPL (256 * ASTR)        // 20480
#define STG (BOFF + BPL)        // 40960
#define NSTAGE 3
#define GEMM_SMEM (NSTAGE * STG)  // 122880

// ACT: 0 none, 1 swish, 2 s6 epilogue. OUTF: 0 split fp16, 1 fp32.
template <int ACT, int OUTF>
__global__ __launch_bounds__(256, 1) void mm_h(
    const __half* __restrict__ Ah, const __half* __restrict__ Al,
    const __half* __restrict__ Wt,
    const float* __restrict__ bias, int Cin, int Cout, int M,
    __half* __restrict__ Yh, __half* __restrict__ Yl, float* __restrict__ Yf,
    const __half* __restrict__ xch, const __half* __restrict__ xcl,
    const __half* __restrict__ xrh, const __half* __restrict__ xrl,
    const float* __restrict__ cbv) {
    extern __shared__ char smem[];
    const uint32_t sb = s2u(smem);
    const int tid = threadIdx.x;
    const int wid = tid >> 5;
    const int lane = tid & 31;
    const int warp_m = wid >> 2;   // 0..1
    const int warp_n = wid & 3;    // 0..3
    const int bm = blockIdx.y * 128;
    const int bn = blockIdx.x * 256;
    const int KC = Cin >> 5;       // 32-wide k chunks per tap
    const int nch = 3 * KC;

    float acc[4][8][4];
#pragma unroll
    for (int i = 0; i < 4; i++)
#pragma unroll
        for (int j = 0; j < 8; j++)
#pragma unroll
            for (int q = 0; q < 4; q++) acc[i][j][q] = 0.f;

    // loader mapping
    const int alr = tid >> 1;              // A row 0..127
    const int aseg = tid & 1;              // 32B half-row
    const int apos = (bm + alr) & LMASK;

    auto issue = [&](int cc) {
        int koff = cc / KC;
        int kc = (cc - koff * KC) << 5;
        uint32_t st = sb + (uint32_t)(cc % NSTAGE) * STG;
        // A planes (hi, lo)
        bool av = !((koff == 0 && apos == 0) || (koff == 2 && apos == LMASK));
        uint32_t asz = av ? 16u : 0u;
        long long ar = (long long)(bm + alr) + koff - 1;
        const __half* ph = Ah + ar * Cin + kc + aseg * 16;
        const __half* pl = Al + ar * Cin + kc + aseg * 16;
        uint32_t sa = st + (uint32_t)alr * ASTR + (uint32_t)aseg * 32;
        cp16(sa, ph, asz);
        cp16(sa + 16, ph + 8, asz);
        cp16(sa + APL, pl, asz);
        cp16(sa + APL + 16, pl + 8, asz);
        // B plane: row n = tid (256 rows)
        size_t bo = ((size_t)koff * Cout + bn + tid) * Cin + kc;
        uint32_t sbb = st + BOFF + (uint32_t)tid * ASTR;
        cp16(sbb, Wt + bo, 16u);
        cp16(sbb + 16, Wt + bo + 8, 16u);
        cp16(sbb + 32, Wt + bo + 16, 16u);
        cp16(sbb + 48, Wt + bo + 24, 16u);
    };

    issue(0); cp_commit();
    issue(1); cp_commit();

    // ldmatrix address components
    const int a_row = warp_m * 64 + (lane & 15);
    const uint32_t a_kb = (uint32_t)(lane >> 4) * 16;  // byte offset (8 halfs)
    const int mi = lane >> 3;
    const int b_row = warp_n * 64 + ((mi >> 1) << 3) + (lane & 7);
    const uint32_t b_kb = (uint32_t)(mi & 1) * 16;

    for (int cc = 0; cc < nch; cc++) {
        if (cc + 1 < nch) cp_wait<1>(); else cp_wait<0>();
        __syncthreads();
        if (cc + 2 < nch) { issue(cc + 2); cp_commit(); }

        uint32_t st = sb + (uint32_t)(cc % NSTAGE) * STG;
#pragma unroll
        for (int k16 = 0; k16 < 2; k16++) {
            uint32_t ah[4][4], al[4][4];
#pragma unroll
            for (int mt = 0; mt < 4; mt++) {
                uint32_t addr = st + (uint32_t)(a_row + mt * 16) * ASTR +
                                (uint32_t)k16 * 32 + a_kb;
                ldsm4(ah[mt], addr);
                ldsm4(al[mt], addr + APL);
            }
            uint32_t bf[8][2];
#pragma unroll
            for (int p = 0; p < 4; p++) {
                uint32_t addr = st + BOFF + (uint32_t)(b_row + p * 16) * ASTR +
                                (uint32_t)k16 * 32 + b_kb;
                uint32_t t4[4];
                ldsm4(t4, addr);
                bf[2 * p][0] = t4[0]; bf[2 * p][1] = t4[1];
                bf[2 * p + 1][0] = t4[2]; bf[2 * p + 1][1] = t4[3];
            }
#pragma unroll
            for (int mt = 0; mt < 4; mt++) {
#pragma unroll
                for (int nt = 0; nt < 8; nt++) {
                    hmma(acc[mt][nt], ah[mt], bf[nt]);
                    hmma(acc[mt][nt], al[mt], bf[nt]);
                }
            }
        }
    }

    // ---------------- epilogue ----------------
    const int erow0 = bm + warp_m * 64 + (lane >> 2);
    const int ecol0 = bn + warp_n * 64 + (lane & 3) * 2;
#pragma unroll
    for (int mt = 0; mt < 4; mt++) {
#pragma unroll
        for (int h = 0; h < 2; h++) {
            int row = erow0 + mt * 16 + h * 8;
            float cbs = 0.f;
            if (ACT == 2) cbs = cbv[row];
            size_t yb = (size_t)row * Cout;
#pragma unroll
            for (int nt = 0; nt < 8; nt++) {
                int col = ecol0 + nt * 8;
                float v0 = acc[mt][nt][2 * h + 0] + bias[col];
                float v1 = acc[mt][nt][2 * h + 1] + bias[col + 1];
                if (ACT == 1) { v0 = swish_f(v0); v1 = swish_f(v1); }
                if (ACT == 2) {
                    size_t o = yb + col;
                    __half2 ch = *(const __half2*)(xch + o);
                    __half2 cl = *(const __half2*)(xcl + o);
                    __half2 rh = *(const __half2*)(xrh + o);
                    __half2 rl = *(const __half2*)(xrl + o);
                    float xc0 = __half2float(ch.x) + __half2float(cl.x);
                    float xc1 = __half2float(ch.y) + __half2float(cl.y);
                    float xr0 = __half2float(rh.x) + __half2float(rl.x);
                    float xr1 = __half2float(rh.y) + __half2float(rl.y);
                    v0 = xc0 * softplus_f(v0) * cbs * xr0;
                    v1 = xc1 * softplus_f(v1) * cbs * xr1;
                }
                if (OUTF == 0) {
                    __half h0 = __float2half_rn(v0);
                    __half h1 = __float2half_rn(v1);
                    __half2 hp; hp.x = h0; hp.y = h1;
                    *(__half2*)(Yh + yb + col) = hp;
                    __half2 lp;
                    lp.x = __float2half_rn(v0 - __half2float(h0));
                    lp.y = __float2half_rn(v1 - __half2float(h1));
                    *(__half2*)(Yl + yb + col) = lp;
                } else {
                    *(float2*)(Yf + yb + col) = make_float2(v0, v1);
                }
            }
        }
    }
}

// ---------------- fused fc2/fc3 conv + cb scalar (reads hi/lo fp16) ----------------
__global__ void bc_kernel(const __half* __restrict__ Xh,
                          const __half* __restrict__ Xl,
                          const float* __restrict__ w2, const float* __restrict__ b2,
                          const float* __restrict__ w3, const float* __restrict__ b3,
                          float* __restrict__ cbout, int M) {
    int warp = (int)((blockIdx.x * blockDim.x + threadIdx.x) >> 5);
    int lane = threadIdx.x & 31;
    if (warp >= M) return;
    float accB[NS], accC[NS];
#pragma unroll
    for (int n = 0; n < NS; n++) { accB[n] = 0.f; accC[n] = 0.f; }
    int pos = warp & LMASK;
    for (int koff = 0; koff < 3; koff++) {
        if ((koff == 0 && pos == 0) || (koff == 2 && pos == LMASK)) continue;
        const __half* xh = Xh + (size_t)(warp + koff - 1) * D2;
        const __half* xl = Xl + (size_t)(warp + koff - 1) * D2;
        const float* w2k = w2 + (size_t)koff * D2 * NS;
        const float* w3k = w3 + (size_t)koff * D2 * NS;
        for (int c = lane; c < D2; c += 32) {
            float xv = __half2float(xh[c]) + __half2float(xl[c]);
            const float4* w2p = (const float4*)(w2k + (size_t)c * NS);
            const float4* w3p = (const float4*)(w3k + (size_t)c * NS);
#pragma unroll
            for (int q = 0; q < 4; q++) {
                float4 wv = w2p[q];
                accB[q * 4 + 0] += xv * wv.x;
                accB[q * 4 + 1] += xv * wv.y;
                accB[q * 4 + 2] += xv * wv.z;
                accB[q * 4 + 3] += xv * wv.w;
                float4 wv3 = w3p[q];
                accC[q * 4 + 0] += xv * wv3.x;
                accC[q * 4 + 1] += xv * wv3.y;
                accC[q * 4 + 2] += xv * wv3.z;
                accC[q * 4 + 3] += xv * wv3.w;
            }
        }
    }
#pragma unroll
    for (int n = 0; n < NS; n++) {
#pragma unroll
        for (int off = 16; off; off >>= 1) {
            accB[n] += __shfl_xor_sync(0xffffffffu, accB[n], off);
            accC[n] += __shfl_xor_sync(0xffffffffu, accC[n], off);
        }
    }
    if (lane == 0) {
        float s = 0.f;
#pragma unroll
        for (int n = 0; n < NS; n++) s += (accB[n] + b2[n]) * (accC[n] + b3[n]);
        cbout[warp] = s;
    }
}

// ---------------- launch ----------------
extern "C" void kernel_launch(void* const* d_in, const int* in_sizes, int n_in,
                              void* d_out, int out_size) {
    const float* x      = (const float*)d_in[0];
    const float* norm_w = (const float*)d_in[1];
    const float* inp_w  = (const float*)d_in[2];
    const float* inp_b  = (const float*)d_in[3];
    const float* conv_w = (const float*)d_in[4];
    const float* conv_b = (const float*)d_in[5];
    const float* cl_w   = (const float*)d_in[6];
    const float* cl_b   = (const float*)d_in[7];
    const float* fc1_w  = (const float*)d_in[8];
    const float* fc1_b  = (const float*)d_in[9];
    const float* fc2_w  = (const float*)d_in[10];
    const float* fc2_b  = (const float*)d_in[11];
    const float* fc3_w  = (const float*)d_in[12];
    const float* fc3_b  = (const float*)d_in[13];
    // d_in[14] = A (mathematically dead)
    const float* res_w  = (const float*)d_in[15];
    const float* res_b  = (const float*)d_in[16];
    const float* out_w  = (const float*)d_in[17];
    const float* out_b  = (const float*)d_in[18];

    int M = in_sizes[0] / D1;  // 16384

    __half *xnh, *xnl, *t0h, *t0l, *t1h, *t1l, *t2h, *t2l;
    __half *wInp, *wCnv, *wCl, *wF1, *wRes, *wOut;
    float* cb;
    cudaGetSymbolAddress((void**)&xnh, g_xnh);
    cudaGetSymbolAddress((void**)&xnl, g_xnl);
    cudaGetSymbolAddress((void**)&t0h, g_t0h);
    cudaGetSymbolAddress((void**)&t0l, g_t0l);
    cudaGetSymbolAddress((void**)&t1h, g_t1h);
    cudaGetSymbolAddress((void**)&t1l, g_t1l);
    cudaGetSymbolAddress((void**)&t2h, g_t2h);
    cudaGetSymbolAddress((void**)&t2l, g_t2l);
    cudaGetSymbolAddress((void**)&cb, g_cb);
    cudaGetSymbolAddress((void**)&wInp, g_wInp);
    cudaGetSymbolAddress((void**)&wCnv, g_wCnv);
    cudaGetSymbolAddress((void**)&wCl, g_wCl);
    cudaGetSymbolAddress((void**)&wF1, g_wF1);
    cudaGetSymbolAddress((void**)&wRes, g_wRes);
    cudaGetSymbolAddress((void**)&wOut, g_wOut);

    cudaFuncSetAttribute(mm_h<0, 0>, cudaFuncAttributeMaxDynamicSharedMemorySize, GEMM_SMEM);
    cudaFuncSetAttribute(mm_h<1, 0>, cudaFuncAttributeMaxDynamicSharedMemorySize, GEMM_SMEM);
    cudaFuncSetAttribute(mm_h<2, 0>, cudaFuncAttributeMaxDynamicSharedMemorySize, GEMM_SMEM);
    cudaFuncSetAttribute(mm_h<0, 1>, cudaFuncAttributeMaxDynamicSharedMemorySize, GEMM_SMEM);

    // weight transpose + fp16
    dim3 wblk(32, 8);
    wtq<<<dim3(D2 / 32, D1 / 32, 3), wblk>>>(inp_w, wInp, D1, D2);
    wtq<<<dim3(D2 / 32, D2 / 32, 3), wblk>>>(conv_w, wCnv, D2, D2);
    wtq<<<dim3(D2 / 32, D2 / 32, 3), wblk>>>(cl_w, wCl, D2, D2);
    wtq<<<dim3(D2 / 32, D2 / 32, 3), wblk>>>(fc1_w, wF1, D2, D2);
    wtq<<<dim3(D2 / 32, D1 / 32, 3), wblk>>>(res_w, wRes, D1, D2);
    wtq<<<dim3(D1 / 32, D2 / 32, 3), wblk>>>(out_w, wOut, D2, D1);

    // 1) xn = rmsnorm(x) -> hi/lo fp16
    rmsnorm_h<<<M, 128>>>(x, norm_w, xnh, xnl);

    dim3 blk(256);
    dim3 g_big(D2 / 256, M / 128);   // 4 x 128
    dim3 g_out(D1 / 256, M / 128);   // 2 x 128

    // 2) t0 = conv(xn, inp)
    mm_h<0, 0><<<g_big, blk, GEMM_SMEM>>>(xnh, xnl, wInp, inp_b, D1, D2, M,
        t0h, t0l, nullptr, nullptr, nullptr, nullptr, nullptr, nullptr);
    // 3) t1 = swish(conv(t0, conv))
    mm_h<1, 0><<<g_big, blk, GEMM_SMEM>>>(t0h, t0l, wCnv, conv_b, D2, D2, M,
        t1h, t1l, nullptr, nullptr, nullptr, nullptr, nullptr, nullptr);
    // 4) t2 = conv(t1, cl) = x_conv_out
    mm_h<0, 0><<<g_big, blk, GEMM_SMEM>>>(t1h, t1l, wCl, cl_b, D2, D2, M,
        t2h, t2l, nullptr, nullptr, nullptr, nullptr, nullptr, nullptr);
    // 5) cb[m]
    bc_kernel<<<(M * 32 + 255) / 256, 256>>>(t2h, t2l, fc2_w, fc2_b, fc3_w, fc3_b, cb, M);
    // 6) t0 = x_res = swish(conv(xn, res))   (t0 free after step 3)
    mm_h<1, 0><<<g_big, blk, GEMM_SMEM>>>(xnh, xnl, wRes, res_b, D1, D2, M,
        t0h, t0l, nullptr, nullptr, nullptr, nullptr, nullptr, nullptr);
    // 7) t1 = x_ssm * x_res (s6 epilogue; xc = t2, xr = t0)
    mm_h<2, 0><<<g_big, blk, GEMM_SMEM>>>(t2h, t2l, wF1, fc1_b, D2, D2, M,
        t1h, t1l, nullptr, t2h, t2l, t0h, t0l, cb);
    // 8) out = conv(t1, out) -> fp32 d_out
    mm_h<0, 1><<<g_out, blk, GEMM_SMEM>>>(t1h, t1l, wOut, out_b, D2, D1, M,
        nullptr, nullptr, (float*)d_out, nullptr, nullptr, nullptr, nullptr, nullptr);
}

// round 6
// speedup vs baseline: 3.7170x; 1.2253x over previous
#include <cuda_runtime.h>
#include <cuda_fp16.h>
#include <math.h>
#include <cstdint>

#define D1 512
#define D2 1024
#define NS 16
#define MTOT 16384
#define LMASK 4095

// ---------------- scratch (static device globals; no allocation) ----------------
__device__ __half g_xnh[(size_t)MTOT * D1], g_xnl[(size_t)MTOT * D1];
__device__ __half g_t0h[(size_t)MTOT * D2], g_t0l[(size_t)MTOT * D2];
__device__ __half g_t1h[(size_t)MTOT * D2], g_t1l[(size_t)MTOT * D2];
__device__ __half g_t2h[(size_t)MTOT * D2], g_t2l[(size_t)MTOT * D2];
__device__ float g_cb[MTOT];
// transposed fp16 weights: [koff][Cout][Cin]
__device__ __half g_wInp[3 * D1 * D2];
__device__ __half g_wCnv[3 * D2 * D2];
__device__ __half g_wCl[3 * D2 * D2];
__device__ __half g_wF1[3 * D2 * D2];
__device__ __half g_wRes[3 * D1 * D2];
__device__ __half g_wOut[3 * D2 * D1];

// ---------------- small math ----------------
__device__ __forceinline__ float softplus_f(float x) {
    return (x > 20.0f) ? x : log1pf(expf(x));
}
__device__ __forceinline__ float swish_f(float x) {
    return x / (1.0f + expf(-x));
}

// ---------------- ptx helpers ----------------
__device__ __forceinline__ uint32_t s2u(const void* p) {
    uint32_t a;
    asm("{ .reg .u64 t; cvta.to.shared.u64 t, %1; cvt.u32.u64 %0, t; }"
        : "=r"(a) : "l"(p));
    return a;
}
__device__ __forceinline__ void cp16(uint32_t saddr, const void* gaddr, uint32_t sz) {
    asm volatile("cp.async.ca.shared.global [%0], [%1], 16, %2;"
                 :: "r"(saddr), "l"(gaddr), "r"(sz) : "memory");
}
__device__ __forceinline__ void cp_commit() {
    asm volatile("cp.async.commit_group;" ::: "memory");
}
template <int N>
__device__ __forceinline__ void cp_wait() {
    asm volatile("cp.async.wait_group %0;" :: "n"(N) : "memory");
}
__device__ __forceinline__ void ldsm4(uint32_t* r, uint32_t addr) {
    asm volatile("ldmatrix.sync.aligned.m8n8.x4.shared.b16 {%0,%1,%2,%3}, [%4];"
                 : "=r"(r[0]), "=r"(r[1]), "=r"(r[2]), "=r"(r[3]) : "r"(addr));
}
__device__ __forceinline__ void hmma(float* d, const uint32_t* a, const uint32_t* b) {
    asm volatile(
        "mma.sync.aligned.m16n8k16.row.col.f32.f16.f16.f32 "
        "{%0,%1,%2,%3}, {%4,%5,%6,%7}, {%8,%9}, {%0,%1,%2,%3};"
        : "+f"(d[0]), "+f"(d[1]), "+f"(d[2]), "+f"(d[3])
        : "r"(a[0]), "r"(a[1]), "r"(a[2]), "r"(a[3]), "r"(b[0]), "r"(b[1]));
}

// ---------------- rmsnorm -> hi/lo fp16 ----------------
__global__ void rmsnorm_h(const float* __restrict__ x,
                          const float* __restrict__ w,
                          __half* __restrict__ yh, __half* __restrict__ yl) {
    int row = blockIdx.x;
    int t = threadIdx.x;  // 128 threads * float4
    const float4* xr = (const float4*)(x + (size_t)row * D1);
    float4 xv = xr[t];
    float ss = xv.x * xv.x + xv.y * xv.y + xv.z * xv.z + xv.w * xv.w;
#pragma unroll
    for (int off = 16; off; off >>= 1) ss += __shfl_xor_sync(0xffffffffu, ss, off);
    __shared__ float sred[4];
    if ((t & 31) == 0) sred[t >> 5] = ss;
    __syncthreads();
    float tot = sred[0] + sred[1] + sred[2] + sred[3];
    float s = rsqrtf(tot * (1.0f / (float)D1) + 1e-5f);
    float4 wv = ((const float4*)w)[t];
    float o[4];
    o[0] = xv.x * s * wv.x; o[1] = xv.y * s * wv.y;
    o[2] = xv.z * s * wv.z; o[3] = xv.w * s * wv.w;
    size_t base = (size_t)row * D1 + t * 4;
#pragma unroll
    for (int j = 0; j < 4; j += 2) {
        __half h0 = __float2half_rn(o[j]);
        __half h1 = __float2half_rn(o[j + 1]);
        __half2 hp; hp.x = h0; hp.y = h1;
        *(__half2*)(yh + base + j) = hp;
        __half2 lp;
        lp.x = __float2half_rn(o[j] - __half2float(h0));
        lp.y = __float2half_rn(o[j + 1] - __half2float(h1));
        *(__half2*)(yl + base + j) = lp;
    }
}

// ---------------- weight transpose + fp16: W[k][Cin][Cout] -> T[k][Cout][Cin] ----------------
__global__ void wtq(const float* __restrict__ W, __half* __restrict__ T,
                    int Cin, int Cout) {
    __shared__ float tile[32][33];
    int koff = blockIdx.z;
    int n0 = blockIdx.x * 32;
    int c0 = blockIdx.y * 32;
    int tx = threadIdx.x, ty = threadIdx.y;  // 32 x 8
    const float* Wk = W + (size_t)koff * Cin * Cout;
#pragma unroll
    for (int r = 0; r < 32; r += 8)
        tile[ty + r][tx] = Wk[(size_t)(c0 + ty + r) * Cout + n0 + tx];
    __syncthreads();
    __half* Tk = T + (size_t)koff * Cout * Cin;
#pragma unroll
    for (int r = 0; r < 32; r += 8)
        Tk[(size_t)(n0 + ty + r) * Cin + c0 + tx] =
            __float2half_rn(tile[tx][ty + r]);
}

// ---------------- fp16 conv-GEMM (mma.sync), 2 CTAs/SM ----------------
// Y[m,n] = act( sum_{koff,c} X[m+koff-1,c] * WT[koff][n][c] + bias[n] )
// X = Xh + Xl (fp16 split), W = fp16. 2 HMMAs per k16.
// CTA 128x128, BK=32, warp 64x32 (2x4 warps), 3-stage cp.async.
#define ASTR 80                  // bytes per smem row (32 halfs + 16B pad)
#define APL (128 * ASTR)         // 10240 per A plane
#define BOFF (2 * APL)           // 20480
#define BPL (128 * ASTR)         // 10240
#define STG (BOFF + BPL)         // 30720
#define NSTAGE 3
#define GEMM_SMEM (NSTAGE * STG) // 92160

// ACT: 0 none, 1 swish, 2 s6 epilogue. OUTF: 0 split fp16, 1 fp32.
template <int ACT, int OUTF>
__global__ __launch_bounds__(256, 2) void mm_h(
    const __half* __restrict__ Ah, const __half* __restrict__ Al,
    const __half* __restrict__ Wt,
    const float* __restrict__ bias, int Cin, int Cout, int M,
    __half* __restrict__ Yh, __half* __restrict__ Yl, float* __restrict__ Yf,
    const __half* __restrict__ xch, const __half* __restrict__ xcl,
    const __half* __restrict__ xrh, const __half* __restrict__ xrl,
    const float* __restrict__ cbv) {
    extern __shared__ char smem[];
    const uint32_t sb = s2u(smem);
    const int tid = threadIdx.x;
    const int wid = tid >> 5;
    const int lane = tid & 31;
    const int warp_m = wid >> 2;   // 0..1
    const int warp_n = wid & 3;    // 0..3
    const int bm = blockIdx.y * 128;
    const int bn = blockIdx.x * 128;
    const int KC = Cin >> 5;       // 32-wide k chunks per tap
    const int nch = 3 * KC;

    float acc[4][4][4];
#pragma unroll
    for (int i = 0; i < 4; i++)
#pragma unroll
        for (int j = 0; j < 4; j++)
#pragma unroll
            for (int q = 0; q < 4; q++) acc[i][j][q] = 0.f;

    // loader mapping: 2 threads per row, 32B each
    const int lr = tid >> 1;               // row 0..127
    const int lseg = tid & 1;
    const int apos = (bm + lr) & LMASK;

    auto issue = [&](int cc) {
        int koff = cc / KC;
        int kc = (cc - koff * KC) << 5;
        uint32_t st = sb + (uint32_t)(cc % NSTAGE) * STG;
        // A planes (hi, lo)
        bool av = !((koff == 0 && apos == 0) || (koff == 2 && apos == LMASK));
        uint32_t asz = av ? 16u : 0u;
        long long ar = (long long)(bm + lr) + koff - 1;
        const __half* ph = Ah + ar * Cin + kc + lseg * 16;
        const __half* pl = Al + ar * Cin + kc + lseg * 16;
        uint32_t sa = st + (uint32_t)lr * ASTR + (uint32_t)lseg * 32;
        cp16(sa, ph, asz);
        cp16(sa + 16, ph + 8, asz);
        cp16(sa + APL, pl, asz);
        cp16(sa + APL + 16, pl + 8, asz);
        // B plane
        size_t bo = ((size_t)koff * Cout + bn + lr) * Cin + kc + lseg * 16;
        uint32_t sbb = st + BOFF + (uint32_t)lr * ASTR + (uint32_t)lseg * 32;
        cp16(sbb, Wt + bo, 16u);
        cp16(sbb + 16, Wt + bo + 8, 16u);
    };

    issue(0); cp_commit();
    issue(1); cp_commit();

    // ldmatrix address components
    const int a_row = warp_m * 64 + (lane & 15);
    const uint32_t a_kb = (uint32_t)(lane >> 4) * 16;
    const int mi = lane >> 3;
    const int b_row = warp_n * 32 + ((mi >> 1) << 3) + (lane & 7);
    const uint32_t b_kb = (uint32_t)(mi & 1) * 16;

    for (int cc = 0; cc < nch; cc++) {
        if (cc + 1 < nch) cp_wait<1>(); else cp_wait<0>();
        __syncthreads();
        if (cc + 2 < nch) { issue(cc + 2); cp_commit(); }

        uint32_t st = sb + (uint32_t)(cc % NSTAGE) * STG;
#pragma unroll
        for (int k16 = 0; k16 < 2; k16++) {
            uint32_t ah[4][4], al[4][4];
#pragma unroll
            for (int mt = 0; mt < 4; mt++) {
                uint32_t addr = st + (uint32_t)(a_row + mt * 16) * ASTR +
                                (uint32_t)k16 * 32 + a_kb;
                ldsm4(ah[mt], addr);
                ldsm4(al[mt], addr + APL);
            }
            uint32_t bf[4][2];
#pragma unroll
            for (int p = 0; p < 2; p++) {
                uint32_t addr = st + BOFF + (uint32_t)(b_row + p * 16) * ASTR +
                                (uint32_t)k16 * 32 + b_kb;
                uint32_t t4[4];
                ldsm4(t4, addr);
                bf[2 * p][0] = t4[0]; bf[2 * p][1] = t4[1];
                bf[2 * p + 1][0] = t4[2]; bf[2 * p + 1][1] = t4[3];
            }
#pragma unroll
            for (int mt = 0; mt < 4; mt++) {
#pragma unroll
                for (int nt = 0; nt < 4; nt++) {
                    hmma(acc[mt][nt], ah[mt], bf[nt]);
                    hmma(acc[mt][nt], al[mt], bf[nt]);
                }
            }
        }
    }

    // ---------------- epilogue ----------------
    const int erow0 = bm + warp_m * 64 + (lane >> 2);
    const int ecol0 = bn + warp_n * 32 + (lane & 3) * 2;
#pragma unroll
    for (int mt = 0; mt < 4; mt++) {
#pragma unroll
        for (int h = 0; h < 2; h++) {
            int row = erow0 + mt * 16 + h * 8;
            float cbs = 0.f;
            if (ACT == 2) cbs = cbv[row];
            size_t yb = (size_t)row * Cout;
#pragma unroll
            for (int nt = 0; nt < 4; nt++) {
                int col = ecol0 + nt * 8;
                float v0 = acc[mt][nt][2 * h + 0] + bias[col];
                float v1 = acc[mt][nt][2 * h + 1] + bias[col + 1];
                if (ACT == 1) { v0 = swish_f(v0); v1 = swish_f(v1); }
                if (ACT == 2) {
                    size_t o = yb + col;
                    __half2 ch = *(const __half2*)(xch + o);
                    __half2 cl = *(const __half2*)(xcl + o);
                    __half2 rh = *(const __half2*)(xrh + o);
                    __half2 rl = *(const __half2*)(xrl + o);
                    float xc0 = __half2float(ch.x) + __half2float(cl.x);
                    float xc1 = __half2float(ch.y) + __half2float(cl.y);
                    float xr0 = __half2float(rh.x) + __half2float(rl.x);
                    float xr1 = __half2float(rh.y) + __half2float(rl.y);
                    v0 = xc0 * softplus_f(v0) * cbs * xr0;
                    v1 = xc1 * softplus_f(v1) * cbs * xr1;
                }
                if (OUTF == 0) {
                    __half h0 = __float2half_rn(v0);
                    __half h1 = __float2half_rn(v1);
                    __half2 hp; hp.x = h0; hp.y = h1;
                    *(__half2*)(Yh + yb + col) = hp;
                    __half2 lp;
                    lp.x = __float2half_rn(v0 - __half2float(h0));
                    lp.y = __float2half_rn(v1 - __half2float(h1));
                    *(__half2*)(Yl + yb + col) = lp;
                } else {
                    *(float2*)(Yf + yb + col) = make_float2(v0, v1);
                }
            }
        }
    }
}

// ---------------- bc: cb[m] = sum_n (conv16(fc2)+b2)*(conv16(fc3)+b3) ----------------
// Block = 128 rows; all weights staged in smem fp16 (192KB); 4 rows per lane pass.
#define BC_SMEM (2 * 3 * D2 * NS * 2)   // 196608 bytes
__global__ __launch_bounds__(256, 1) void bc2(
    const __half* __restrict__ Xh, const __half* __restrict__ Xl,
    const float* __restrict__ w2, const float* __restrict__ b2,
    const float* __restrict__ w3, const float* __restrict__ b3,
    float* __restrict__ cbout, int M) {
    extern __shared__ __half ws[];
    __half* w2s = ws;                       // [3*D2*NS]
    __half* w3s = ws + 3 * D2 * NS;
    const int tid = threadIdx.x;
    const int wid = tid >> 5;
    const int lane = tid & 31;
    const int bm = blockIdx.x * 128;

    for (int i = tid; i < 3 * D2 * NS; i += 256) {
        w2s[i] = __float2half_rn(w2[i]);
        w3s[i] = __float2half_rn(w3[i]);
    }
    __syncthreads();

    // each warp: 16 rows, processed 4 at a time
    for (int g = 0; g < 4; g++) {
        int r0 = bm + wid * 16 + g * 4;
        float accB[4][NS], accC[4][NS];
#pragma unroll
        for (int j = 0; j < 4; j++)
#pragma unroll
            for (int n = 0; n < NS; n++) { accB[j][n] = 0.f; accC[j][n] = 0.f; }

        for (int koff = 0; koff < 3; koff++) {
            const __half* xh0 = Xh + (size_t)(r0 + koff - 1) * D2;
            const __half* xl0 = Xl + (size_t)(r0 + koff - 1) * D2;
            bool val[4];
#pragma unroll
            for (int j = 0; j < 4; j++) {
                int pos = (r0 + j) & LMASK;
                val[j] = !((koff == 0 && pos == 0) || (koff == 2 && pos == LMASK));
            }
            const __half* w2k = w2s + koff * D2 * NS;
            const __half* w3k = w3s + koff * D2 * NS;
            for (int kk = lane; kk < D2; kk += 32) {
                float xv[4];
#pragma unroll
                for (int j = 0; j < 4; j++) {
                    size_t o = (size_t)j * D2 + kk;
                    xv[j] = val[j] ? (__half2float(xh0[o]) + __half2float(xl0[o]))
                                   : 0.f;
                }
                const __half2* wb = (const __half2*)(w2k + kk * NS);
                const __half2* wc = (const __half2*)(w3k + kk * NS);
#pragma unroll
                for (int q = 0; q < 8; q++) {
                    float2 fb = __half22float2(wb[q]);
                    float2 fc = __half22float2(wc[q]);
#pragma unroll
                    for (int j = 0; j < 4; j++) {
                        accB[j][2 * q] += xv[j] * fb.x;
                        accB[j][2 * q + 1] += xv[j] * fb.y;
                        accC[j][2 * q] += xv[j] * fc.x;
                        accC[j][2 * q + 1] += xv[j] * fc.y;
                    }
                }
            }
        }
        // reduce across lanes and combine
#pragma unroll
        for (int j = 0; j < 4; j++) {
#pragma unroll
            for (int n = 0; n < NS; n++) {
#pragma unroll
                for (int off = 16; off; off >>= 1) {
                    accB[j][n] += __shfl_xor_sync(0xffffffffu, accB[j][n], off);
                    accC[j][n] += __shfl_xor_sync(0xffffffffu, accC[j][n], off);
                }
            }
            if (lane == 0) {
                float s = 0.f;
#pragma unroll
                for (int n = 0; n < NS; n++)
                    s += (accB[j][n] + b2[n]) * (accC[j][n] + b3[n]);
                cbout[r0 + j] = s;
            }
        }
    }
}

// ---------------- launch ----------------
extern "C" void kernel_launch(void* const* d_in, const int* in_sizes, int n_in,
                              void* d_out, int out_size) {
    const float* x      = (const float*)d_in[0];
    const float* norm_w = (const float*)d_in[1];
    const float* inp_w  = (const float*)d_in[2];
    const float* inp_b  = (const float*)d_in[3];
    const float* conv_w = (const float*)d_in[4];
    const float* conv_b = (const float*)d_in[5];
    const float* cl_w   = (const float*)d_in[6];
    const float* cl_b   = (const float*)d_in[7];
    const float* fc1_w  = (const float*)d_in[8];
    const float* fc1_b  = (const float*)d_in[9];
    const float* fc2_w  = (const float*)d_in[10];
    const float* fc2_b  = (const float*)d_in[11];
    const float* fc3_w  = (const float*)d_in[12];
    const float* fc3_b  = (const float*)d_in[13];
    // d_in[14] = A (mathematically dead)
    const float* res_w  = (const float*)d_in[15];
    const float* res_b  = (const float*)d_in[16];
    const float* out_w  = (const float*)d_in[17];
    const float* out_b  = (const float*)d_in[18];

    int M = in_sizes[0] / D1;  // 16384

    __half *xnh, *xnl, *t0h, *t0l, *t1h, *t1l, *t2h, *t2l;
    __half *wInp, *wCnv, *wCl, *wF1, *wRes, *wOut;
    float* cb;
    cudaGetSymbolAddress((void**)&xnh, g_xnh);
    cudaGetSymbolAddress((void**)&xnl, g_xnl);
    cudaGetSymbolAddress((void**)&t0h, g_t0h);
    cudaGetSymbolAddress((void**)&t0l, g_t0l);
    cudaGetSymbolAddress((void**)&t1h, g_t1h);
    cudaGetSymbolAddress((void**)&t1l, g_t1l);
    cudaGetSymbolAddress((void**)&t2h, g_t2h);
    cudaGetSymbolAddress((void**)&t2l, g_t2l);
    cudaGetSymbolAddress((void**)&cb, g_cb);
    cudaGetSymbolAddress((void**)&wInp, g_wInp);
    cudaGetSymbolAddress((void**)&wCnv, g_wCnv);
    cudaGetSymbolAddress((void**)&wCl, g_wCl);
    cudaGetSymbolAddress((void**)&wF1, g_wF1);
    cudaGetSymbolAddress((void**)&wRes, g_wRes);
    cudaGetSymbolAddress((void**)&wOut, g_wOut);

    cudaFuncSetAttribute(mm_h<0, 0>, cudaFuncAttributeMaxDynamicSharedMemorySize, GEMM_SMEM);
    cudaFuncSetAttribute(mm_h<1, 0>, cudaFuncAttributeMaxDynamicSharedMemorySize, GEMM_SMEM);
    cudaFuncSetAttribute(mm_h<2, 0>, cudaFuncAttributeMaxDynamicSharedMemorySize, GEMM_SMEM);
    cudaFuncSetAttribute(mm_h<0, 1>, cudaFuncAttributeMaxDynamicSharedMemorySize, GEMM_SMEM);
    cudaFuncSetAttribute(bc2, cudaFuncAttributeMaxDynamicSharedMemorySize, BC_SMEM);

    // weight transpose + fp16
    dim3 wblk(32, 8);
    wtq<<<dim3(D2 / 32, D1 / 32, 3), wblk>>>(inp_w, wInp, D1, D2);
    wtq<<<dim3(D2 / 32, D2 / 32, 3), wblk>>>(conv_w, wCnv, D2, D2);
    wtq<<<dim3(D2 / 32, D2 / 32, 3), wblk>>>(cl_w, wCl, D2, D2);
    wtq<<<dim3(D2 / 32, D2 / 32, 3), wblk>>>(fc1_w, wF1, D2, D2);
    wtq<<<dim3(D2 / 32, D1 / 32, 3), wblk>>>(res_w, wRes, D1, D2);
    wtq<<<dim3(D1 / 32, D2 / 32, 3), wblk>>>(out_w, wOut, D2, D1);

    // 1) xn = rmsnorm(x) -> hi/lo fp16
    rmsnorm_h<<<M, 128>>>(x, norm_w, xnh, xnl);

    dim3 blk(256);
    dim3 g_big(D2 / 128, M / 128);   // 8 x 128
    dim3 g_out(D1 / 128, M / 128);   // 4 x 128

    // 2) t0 = conv(xn, inp)
    mm_h<0, 0><<<g_big, blk, GEMM_SMEM>>>(xnh, xnl, wInp, inp_b, D1, D2, M,
        t0h, t0l, nullptr, nullptr, nullptr, nullptr, nullptr, nullptr);
    // 3) t1 = swish(conv(t0, conv))
    mm_h<1, 0><<<g_big, blk, GEMM_SMEM>>>(t0h, t0l, wCnv, conv_b, D2, D2, M,
        t1h, t1l, nullptr, nullptr, nullptr, nullptr, nullptr, nullptr);
    // 4) t2 = conv(t1, cl) = x_conv_out
    mm_h<0, 0><<<g_big, blk, GEMM_SMEM>>>(t1h, t1l, wCl, cl_b, D2, D2, M,
        t2h, t2l, nullptr, nullptr, nullptr, nullptr, nullptr, nullptr);
    // 5) cb[m]
    bc2<<<M / 128, 256, BC_SMEM>>>(t2h, t2l, fc2_w, fc2_b, fc3_w, fc3_b, cb, M);
    // 6) t0 = x_res = swish(conv(xn, res))
    mm_h<1, 0><<<g_big, blk, GEMM_SMEM>>>(xnh, xnl, wRes, res_b, D1, D2, M,
        t0h, t0l, nullptr, nullptr, nullptr, nullptr, nullptr, nullptr);
    // 7) t1 = x_ssm * x_res (s6 epilogue; xc = t2, xr = t0)
    mm_h<2, 0><<<g_big, blk, GEMM_SMEM>>>(t2h, t2l, wF1, fc1_b, D2, D2, M,
        t1h, t1l, nullptr, t2h, t2l, t0h, t0l, cb);
    // 8) out = conv(t1, out) -> fp32 d_out
    mm_h<0, 1><<<g_out, blk, GEMM_SMEM>>>(t1h, t1l, wOut, out_b, D2, D1, M,
        nullptr, nullptr, (float*)d_out, nullptr, nullptr, nullptr, nullptr, nullptr);
}

// round 7
// speedup vs baseline: 3.9974x; 1.0754x over previous
#include <cuda_runtime.h>
#include <cuda_fp16.h>
#include <math.h>
#include <cstdint>

#define D1 512
#define D2 1024
#define NS 16
#define MTOT 16384
#define LMASK 4095

// ---------------- scratch (static device globals; no allocation) ----------------
__device__ __half g_xnh[(size_t)MTOT * D1], g_xnl[(size_t)MTOT * D1];
__device__ __half g_t0h[(size_t)MTOT * D2], g_t0l[(size_t)MTOT * D2];
__device__ __half g_t1h[(size_t)MTOT * D2], g_t1l[(size_t)MTOT * D2];
__device__ __half g_t2h[(size_t)MTOT * D2], g_t2l[(size_t)MTOT * D2];
__device__ __half g_t3h[(size_t)MTOT * D2], g_t3l[(size_t)MTOT * D2];
__device__ float g_cb[MTOT];
// transposed fp16 weights
__device__ __half g_wIR[3 * 2048 * D1];     // inp rows 0-1023, res rows 1024-2047
__device__ __half g_wCnv[3 * D2 * D2];
__device__ __half g_wCl[3 * D2 * D2];
__device__ __half g_wF1[3 * D2 * D2];
__device__ __half g_wOut[3 * D1 * D2];      // [koff][512][1024]
__device__ float g_biasIR[2048];

// ---------------- small math ----------------
__device__ __forceinline__ float softplus_f(float x) {
    return (x > 20.0f) ? x : log1pf(expf(x));
}
__device__ __forceinline__ float swish_f(float x) {
    return x / (1.0f + expf(-x));
}

// ---------------- ptx helpers ----------------
__device__ __forceinline__ uint32_t s2u(const void* p) {
    uint32_t a;
    asm("{ .reg .u64 t; cvta.to.shared.u64 t, %1; cvt.u32.u64 %0, t; }"
        : "=r"(a) : "l"(p));
    return a;
}
__device__ __forceinline__ void cp16(uint32_t saddr, const void* gaddr, uint32_t sz) {
    asm volatile("cp.async.ca.shared.global [%0], [%1], 16, %2;"
                 :: "r"(saddr), "l"(gaddr), "r"(sz) : "memory");
}
__device__ __forceinline__ void cp_commit() {
    asm volatile("cp.async.commit_group;" ::: "memory");
}
template <int N>
__device__ __forceinline__ void cp_wait() {
    asm volatile("cp.async.wait_group %0;" :: "n"(N) : "memory");
}
__device__ __forceinline__ void ldsm4(uint32_t* r, uint32_t addr) {
    asm volatile("ldmatrix.sync.aligned.m8n8.x4.shared.b16 {%0,%1,%2,%3}, [%4];"
                 : "=r"(r[0]), "=r"(r[1]), "=r"(r[2]), "=r"(r[3]) : "r"(addr));
}
__device__ __forceinline__ void hmma(float* d, const uint32_t* a, const uint32_t* b) {
    asm volatile(
        "mma.sync.aligned.m16n8k16.row.col.f32.f16.f16.f32 "
        "{%0,%1,%2,%3}, {%4,%5,%6,%7}, {%8,%9}, {%0,%1,%2,%3};"
        : "+f"(d[0]), "+f"(d[1]), "+f"(d[2]), "+f"(d[3])
        : "r"(a[0]), "r"(a[1]), "r"(a[2]), "r"(a[3]), "r"(b[0]), "r"(b[1]));
}

// ---------------- unified prep: weight transposes + rmsnorm + bias concat ----------------
// blocks [0,13824): wtq; [13824,22016): rmsnorm (2 rows each); [22016,22024): biasIR
__global__ __launch_bounds__(256) void prep(
    const float* __restrict__ x, const float* __restrict__ norm_w,
    const float* __restrict__ inp_w, const float* __restrict__ conv_w,
    const float* __restrict__ cl_w, const float* __restrict__ fc1_w,
    const float* __restrict__ res_w, const float* __restrict__ out_w,
    const float* __restrict__ inp_b, const float* __restrict__ res_b,
    __half* __restrict__ xnh, __half* __restrict__ xnl,
    __half* __restrict__ wIR, __half* __restrict__ wCnv,
    __half* __restrict__ wCl, __half* __restrict__ wF1,
    __half* __restrict__ wOut, float* __restrict__ biasIR) {
    __shared__ float tile[32][33];
    __shared__ float sred[2][4];
    int lb = blockIdx.x;
    int tid = threadIdx.x;
    if (lb < 13824) {
        const float* W; __half* T; int Cin, Cout, rowoff, rowtot, base;
        if (lb < 1536)       { W = inp_w;  T = wIR;  Cin = 512;  Cout = 1024; rowoff = 0;    rowtot = 2048; base = 0; }
        else if (lb < 4608)  { W = conv_w; T = wCnv; Cin = 1024; Cout = 1024; rowoff = 0;    rowtot = 1024; base = 1536; }
        else if (lb < 7680)  { W = cl_w;   T = wCl;  Cin = 1024; Cout = 1024; rowoff = 0;    rowtot = 1024; base = 4608; }
        else if (lb < 10752) { W = fc1_w;  T = wF1;  Cin = 1024; Cout = 1024; rowoff = 0;    rowtot = 1024; base = 7680; }
        else if (lb < 12288) { W = res_w;  T = wIR;  Cin = 512;  Cout = 1024; rowoff = 1024; rowtot = 2048; base = 10752; }
        else                 { W = out_w;  T = wOut; Cin = 1024; Cout = 512;  rowoff = 0;    rowtot = 512;  base = 12288; }
        int l = lb - base;
        int nx = Cout / 32;
        int bx = l % nx;
        int rest = l / nx;
        int ny = Cin / 32;
        int by = rest % ny;
        int koff = rest / ny;
        int n0 = bx * 32, c0 = by * 32;
        int tx = tid & 31, ty = tid >> 5;
        const float* Wk = W + (size_t)koff * Cin * Cout;
#pragma unroll
        for (int r = 0; r < 32; r += 8)
            tile[ty + r][tx] = Wk[(size_t)(c0 + ty + r) * Cout + n0 + tx];
        __syncthreads();
        __half* Tk = T + (size_t)koff * rowtot * Cin;
#pragma unroll
        for (int r = 0; r < 32; r += 8)
            Tk[(size_t)(rowoff + n0 + ty + r) * Cin + c0 + tx] =
                __float2half_rn(tile[tx][ty + r]);
    } else if (lb < 22016) {
        int rb = lb - 13824;
        int row = rb * 2 + (tid >> 7);
        int t = tid & 127;
        int sr = tid >> 7;
        const float4* xr = (const float4*)(x + (size_t)row * D1);
        float4 xv = xr[t];
        float ss = xv.x * xv.x + xv.y * xv.y + xv.z * xv.z + xv.w * xv.w;
#pragma unroll
        for (int off = 16; off; off >>= 1)
            ss += __shfl_xor_sync(0xffffffffu, ss, off);
        if ((t & 31) == 0) sred[sr][t >> 5] = ss;
        __syncthreads();
        float tot = sred[sr][0] + sred[sr][1] + sred[sr][2] + sred[sr][3];
        float s = rsqrtf(tot * (1.0f / (float)D1) + 1e-5f);
        float4 wv = ((const float4*)norm_w)[t];
        float o[4];
        o[0] = xv.x * s * wv.x; o[1] = xv.y * s * wv.y;
        o[2] = xv.z * s * wv.z; o[3] = xv.w * s * wv.w;
        size_t base = (size_t)row * D1 + t * 4;
#pragma unroll
        for (int j = 0; j < 4; j += 2) {
            __half h0 = __float2half_rn(o[j]);
            __half h1 = __float2half_rn(o[j + 1]);
            __half2 hp; hp.x = h0; hp.y = h1;
            *(__half2*)(xnh + base + j) = hp;
            __half2 lp;
            lp.x = __float2half_rn(o[j] - __half2float(h0));
            lp.y = __float2half_rn(o[j + 1] - __half2float(h1));
            *(__half2*)(xnl + base + j) = lp;
        }
    } else {
        int i = (lb - 22016) * 256 + tid;
        biasIR[i] = (i < D2) ? inp_b[i] : res_b[i - D2];
    }
}

// ---------------- fp16 conv-GEMM (mma.sync), 2 CTAs/SM, warp tile 32x64 ----------------
// Y[m,n] = act( sum_{koff,c} X[m+koff-1,c] * WT[koff][n][c] + bias[n] )
// X = Xh + Xl (fp16 split), W = fp16. 2 HMMAs per k16.
// CTA 128x128, BK=32, warp grid 4x2, 3-stage cp.async.
#define ASTR 80                  // bytes per smem row (32 halfs + 16B pad)
#define APL (128 * ASTR)         // 10240 per A plane
#define BOFF (2 * APL)           // 20480
#define BPL (128 * ASTR)         // 10240
#define STG (BOFF + BPL)         // 30720
#define NSTAGE 3
#define GEMM_SMEM (NSTAGE * STG) // 92160

// ACT: 0 none, 1 swish, 2 s6 epilogue, 3 dual (plain->Y / swish->Y2, stride D2).
// OUTF: 0 split fp16, 1 fp32.
template <int ACT, int OUTF>
__global__ __launch_bounds__(256, 2) void mm_h(
    const __half* __restrict__ Ah, const __half* __restrict__ Al,
    const __half* __restrict__ Wt,
    const float* __restrict__ bias, int Cin, int Cout, int M,
    __half* __restrict__ Yh, __half* __restrict__ Yl, float* __restrict__ Yf,
    __half* __restrict__ Y2h, __half* __restrict__ Y2l,
    const __half* __restrict__ xch, const __half* __restrict__ xcl,
    const __half* __restrict__ xrh, const __half* __restrict__ xrl,
    const float* __restrict__ cbv) {
    extern __shared__ char smem[];
    const uint32_t sb = s2u(smem);
    const int tid = threadIdx.x;
    const int wid = tid >> 5;
    const int lane = tid & 31;
    const int warp_m = wid >> 1;   // 0..3 (32 rows each)
    const int warp_n = wid & 1;    // 0..1 (64 cols each)
    const int bm = blockIdx.y * 128;
    const int bn = blockIdx.x * 128;
    const int KC = Cin >> 5;
    const int nch = 3 * KC;

    float acc[2][8][4];
#pragma unroll
    for (int i = 0; i < 2; i++)
#pragma unroll
        for (int j = 0; j < 8; j++)
#pragma unroll
            for (int q = 0; q < 4; q++) acc[i][j][q] = 0.f;

    // loader mapping: 2 threads per row, 32B each
    const int lr = tid >> 1;
    const int lseg = tid & 1;
    const int apos = (bm + lr) & LMASK;

    auto issue = [&](int cc) {
        int koff = cc / KC;
        int kc = (cc - koff * KC) << 5;
        uint32_t st = sb + (uint32_t)(cc % NSTAGE) * STG;
        bool av = !((koff == 0 && apos == 0) || (koff == 2 && apos == LMASK));
        uint32_t asz = av ? 16u : 0u;
        long long ar = (long long)(bm + lr) + koff - 1;
        const __half* ph = Ah + ar * Cin + kc + lseg * 16;
        const __half* pl = Al + ar * Cin + kc + lseg * 16;
        uint32_t sa = st + (uint32_t)lr * ASTR + (uint32_t)lseg * 32;
        cp16(sa, ph, asz);
        cp16(sa + 16, ph + 8, asz);
        cp16(sa + APL, pl, asz);
        cp16(sa + APL + 16, pl + 8, asz);
        size_t bo = ((size_t)koff * Cout + bn + lr) * Cin + kc + lseg * 16;
        uint32_t sbb = st + BOFF + (uint32_t)lr * ASTR + (uint32_t)lseg * 32;
        cp16(sbb, Wt + bo, 16u);
        cp16(sbb + 16, Wt + bo + 8, 16u);
    };

    issue(0); cp_commit();
    issue(1); cp_commit();

    // ldmatrix address components
    const int a_row = warp_m * 32 + (lane & 15);
    const uint32_t a_kb = (uint32_t)(lane >> 4) * 16;
    const int mi = lane >> 3;
    const int b_row = warp_n * 64 + ((mi >> 1) << 3) + (lane & 7);
    const uint32_t b_kb = (uint32_t)(mi & 1) * 16;

    for (int cc = 0; cc < nch; cc++) {
        if (cc + 1 < nch) cp_wait<1>(); else cp_wait<0>();
        __syncthreads();
        if (cc + 2 < nch) { issue(cc + 2); cp_commit(); }

        uint32_t st = sb + (uint32_t)(cc % NSTAGE) * STG;
#pragma unroll
        for (int k16 = 0; k16 < 2; k16++) {
            uint32_t ah[2][4], al[2][4];
#pragma unroll
            for (int mt = 0; mt < 2; mt++) {
                uint32_t addr = st + (uint32_t)(a_row + mt * 16) * ASTR +
                                (uint32_t)k16 * 32 + a_kb;
                ldsm4(ah[mt], addr);
                ldsm4(al[mt], addr + APL);
            }
            uint32_t bf[8][2];
#pragma unroll
            for (int p = 0; p < 4; p++) {
                uint32_t addr = st + BOFF + (uint32_t)(b_row + p * 16) * ASTR +
                                (uint32_t)k16 * 32 + b_kb;
                uint32_t t4[4];
                ldsm4(t4, addr);
                bf[2 * p][0] = t4[0]; bf[2 * p][1] = t4[1];
                bf[2 * p + 1][0] = t4[2]; bf[2 * p + 1][1] = t4[3];
            }
#pragma unroll
            for (int mt = 0; mt < 2; mt++) {
#pragma unroll
                for (int nt = 0; nt < 8; nt++) {
                    hmma(acc[mt][nt], ah[mt], bf[nt]);
                    hmma(acc[mt][nt], al[mt], bf[nt]);
                }
            }
        }
    }

    // ---------------- epilogue ----------------
    const int erow0 = bm + warp_m * 32 + (lane >> 2);
    const int ecol0 = bn + warp_n * 64 + (lane & 3) * 2;
    const bool isres = (ACT == 3) && (bn >= D2);
    const __half* obh = (ACT == 3) ? (isres ? Y2h : Yh) : Yh;
    const __half* obl = (ACT == 3) ? (isres ? Y2l : Yl) : Yl;
    const int coff = isres ? D2 : 0;
    const int ostride = (ACT == 3) ? D2 : Cout;
#pragma unroll
    for (int mt = 0; mt < 2; mt++) {
#pragma unroll
        for (int h = 0; h < 2; h++) {
            int row = erow0 + mt * 16 + h * 8;
            float cbs = 0.f;
            if (ACT == 2) cbs = cbv[row];
            size_t yb = (size_t)row * ostride;
#pragma unroll
            for (int nt = 0; nt < 8; nt++) {
                int col = ecol0 + nt * 8;
                float v0 = acc[mt][nt][2 * h + 0] + bias[col];
                float v1 = acc[mt][nt][2 * h + 1] + bias[col + 1];
                if (ACT == 1) { v0 = swish_f(v0); v1 = swish_f(v1); }
                if (ACT == 3 && isres) { v0 = swish_f(v0); v1 = swish_f(v1); }
                if (ACT == 2) {
                    size_t o = yb + col;
                    __half2 ch = *(const __half2*)(xch + o);
                    __half2 cl = *(const __half2*)(xcl + o);
                    __half2 rh = *(const __half2*)(xrh + o);
                    __half2 rl = *(const __half2*)(xrl + o);
                    float xc0 = __half2float(ch.x) + __half2float(cl.x);
                    float xc1 = __half2float(ch.y) + __half2float(cl.y);
                    float xr0 = __half2float(rh.x) + __half2float(rl.x);
                    float xr1 = __half2float(rh.y) + __half2float(rl.y);
                    v0 = xc0 * softplus_f(v0) * cbs * xr0;
                    v1 = xc1 * softplus_f(v1) * cbs * xr1;
                }
                if (OUTF == 0) {
                    size_t o = yb + col - coff;
                    __half h0 = __float2half_rn(v0);
                    __half h1 = __float2half_rn(v1);
                    __half2 hp; hp.x = h0; hp.y = h1;
                    *(__half2*)((__half*)obh + o) = hp;
                    __half2 lp;
                    lp.x = __float2half_rn(v0 - __half2float(h0));
                    lp.y = __float2half_rn(v1 - __half2float(h1));
                    *(__half2*)((__half*)obl + o) = lp;
                } else {
                    *(float2*)(Yf + yb + col) = make_float2(v0, v1);
                }
            }
        }
    }
}

// ---------------- bc: cb[m] = sum_n (conv16(fc2)+b2)*(conv16(fc3)+b3) ----------------
#define BC_SMEM (2 * 3 * D2 * NS * 2)   // 196608 bytes
__global__ __launch_bounds__(256, 1) void bc2(
    const __half* __restrict__ Xh, const __half* __restrict__ Xl,
    const float* __restrict__ w2, const float* __restrict__ b2,
    const float* __restrict__ w3, const float* __restrict__ b3,
    float* __restrict__ cbout, int M) {
    extern __shared__ __half ws[];
    __half* w2s = ws;
    __half* w3s = ws + 3 * D2 * NS;
    const int tid = threadIdx.x;
    const int wid = tid >> 5;
    const int lane = tid & 31;
    const int bm = blockIdx.x * 128;

    for (int i = tid; i < 3 * D2 * NS; i += 256) {
        w2s[i] = __float2half_rn(w2[i]);
        w3s[i] = __float2half_rn(w3[i]);
    }
    __syncthreads();

    for (int g = 0; g < 4; g++) {
        int r0 = bm + wid * 16 + g * 4;
        float accB[4][NS], accC[4][NS];
#pragma unroll
        for (int j = 0; j < 4; j++)
#pragma unroll
            for (int n = 0; n < NS; n++) { accB[j][n] = 0.f; accC[j][n] = 0.f; }

        for (int koff = 0; koff < 3; koff++) {
            const __half* xh0 = Xh + (size_t)(r0 + koff - 1) * D2;
            const __half* xl0 = Xl + (size_t)(r0 + koff - 1) * D2;
            bool val[4];
#pragma unroll
            for (int j = 0; j < 4; j++) {
                int pos = (r0 + j) & LMASK;
                val[j] = !((koff == 0 && pos == 0) || (koff == 2 && pos == LMASK));
            }
            const __half* w2k = w2s + koff * D2 * NS;
            const __half* w3k = w3s + koff * D2 * NS;
            for (int kk = lane; kk < D2; kk += 32) {
                float xv[4];
#pragma unroll
                for (int j = 0; j < 4; j++) {
                    size_t o = (size_t)j * D2 + kk;
                    xv[j] = val[j] ? (__half2float(xh0[o]) + __half2float(xl0[o]))
                                   : 0.f;
                }
                const __half2* wb = (const __half2*)(w2k + kk * NS);
                const __half2* wc = (const __half2*)(w3k + kk * NS);
#pragma unroll
                for (int q = 0; q < 8; q++) {
                    float2 fb = __half22float2(wb[q]);
                    float2 fc = __half22float2(wc[q]);
#pragma unroll
                    for (int j = 0; j < 4; j++) {
                        accB[j][2 * q] += xv[j] * fb.x;
                        accB[j][2 * q + 1] += xv[j] * fb.y;
                        accC[j][2 * q] += xv[j] * fc.x;
                        accC[j][2 * q + 1] += xv[j] * fc.y;
                    }
                }
            }
        }
#pragma unroll
        for (int j = 0; j < 4; j++) {
#pragma unroll
            for (int n = 0; n < NS; n++) {
#pragma unroll
                for (int off = 16; off; off >>= 1) {
                    accB[j][n] += __shfl_xor_sync(0xffffffffu, accB[j][n], off);
                    accC[j][n] += __shfl_xor_sync(0xffffffffu, accC[j][n], off);
                }
            }
            if (lane == 0) {
                float s = 0.f;
#pragma unroll
                for (int n = 0; n < NS; n++)
                    s += (accB[j][n] + b2[n]) * (accC[j][n] + b3[n]);
                cbout[r0 + j] = s;
            }
        }
    }
}

// ---------------- launch ----------------
extern "C" void kernel_launch(void* const* d_in, const int* in_sizes, int n_in,
                              void* d_out, int out_size) {
    const float* x      = (const float*)d_in[0];
    const float* norm_w = (const float*)d_in[1];
    const float* inp_w  = (const float*)d_in[2];
    const float* inp_b  = (const float*)d_in[3];
    const float* conv_w = (const float*)d_in[4];
    const float* conv_b = (const float*)d_in[5];
    const float* cl_w   = (const float*)d_in[6];
    const float* cl_b   = (const float*)d_in[7];
    const float* fc1_w  = (const float*)d_in[8];
    const float* fc1_b  = (const float*)d_in[9];
    const float* fc2_w  = (const float*)d_in[10];
    const float* fc2_b  = (const float*)d_in[11];
    const float* fc3_w  = (const float*)d_in[12];
    const float* fc3_b  = (const float*)d_in[13];
    // d_in[14] = A (mathematically dead)
    const float* res_w  = (const float*)d_in[15];
    const float* res_b  = (const float*)d_in[16];
    const float* out_w  = (const float*)d_in[17];
    const float* out_b  = (const float*)d_in[18];

    int M = in_sizes[0] / D1;  // 16384

    __half *xnh, *xnl, *t0h, *t0l, *t1h, *t1l, *t2h, *t2l, *t3h, *t3l;
    __half *wIR, *wCnv, *wCl, *wF1, *wOut;
    float *cb, *biasIR;
    cudaGetSymbolAddress((void**)&xnh, g_xnh);
    cudaGetSymbolAddress((void**)&xnl, g_xnl);
    cudaGetSymbolAddress((void**)&t0h, g_t0h);
    cudaGetSymbolAddress((void**)&t0l, g_t0l);
    cudaGetSymbolAddress((void**)&t1h, g_t1h);
    cudaGetSymbolAddress((void**)&t1l, g_t1l);
    cudaGetSymbolAddress((void**)&t2h, g_t2h);
    cudaGetSymbolAddress((void**)&t2l, g_t2l);
    cudaGetSymbolAddress((void**)&t3h, g_t3h);
    cudaGetSymbolAddress((void**)&t3l, g_t3l);
    cudaGetSymbolAddress((void**)&cb, g_cb);
    cudaGetSymbolAddress((void**)&wIR, g_wIR);
    cudaGetSymbolAddress((void**)&wCnv, g_wCnv);
    cudaGetSymbolAddress((void**)&wCl, g_wCl);
    cudaGetSymbolAddress((void**)&wF1, g_wF1);
    cudaGetSymbolAddress((void**)&wOut, g_wOut);
    cudaGetSymbolAddress((void**)&biasIR, g_biasIR);

    cudaFuncSetAttribute(mm_h<0, 0>, cudaFuncAttributeMaxDynamicSharedMemorySize, GEMM_SMEM);
    cudaFuncSetAttribute(mm_h<1, 0>, cudaFuncAttributeMaxDynamicSharedMemorySize, GEMM_SMEM);
    cudaFuncSetAttribute(mm_h<2, 0>, cudaFuncAttributeMaxDynamicSharedMemorySize, GEMM_SMEM);
    cudaFuncSetAttribute(mm_h<3, 0>, cudaFuncAttributeMaxDynamicSharedMemorySize, GEMM_SMEM);
    cudaFuncSetAttribute(mm_h<0, 1>, cudaFuncAttributeMaxDynamicSharedMemorySize, GEMM_SMEM);
    cudaFuncSetAttribute(bc2, cudaFuncAttributeMaxDynamicSharedMemorySize, BC_SMEM);

    // 1) prep: all weight transposes + rmsnorm + bias concat (one launch)
    prep<<<22024, 256>>>(x, norm_w, inp_w, conv_w, cl_w, fc1_w, res_w, out_w,
                         inp_b, res_b, xnh, xnl, wIR, wCnv, wCl, wF1, wOut, biasIR);

    dim3 blk(256);
    dim3 g_fuse(2048 / 128, M / 128);  // 16 x 128
    dim3 g_big(D2 / 128, M / 128);     // 8 x 128
    dim3 g_out(D1 / 128, M / 128);     // 4 x 128

    // 2) fused: t0 = conv(xn, inp) [cols 0-1023]; t3 = swish(conv(xn, res)) [cols 1024-2047]
    mm_h<3, 0><<<g_fuse, blk, GEMM_SMEM>>>(xnh, xnl, wIR, biasIR, D1, 2048, M,
        t0h, t0l, nullptr, t3h, t3l, nullptr, nullptr, nullptr, nullptr, nullptr);
    // 3) t1 = swish(conv(t0, conv))
    mm_h<1, 0><<<g_big, blk, GEMM_SMEM>>>(t0h, t0l, wCnv, conv_b, D2, D2, M,
        t1h, t1l, nullptr, nullptr, nullptr, nullptr, nullptr, nullptr, nullptr, nullptr);
    // 4) t2 = conv(t1, cl) = x_conv_out
    mm_h<0, 0><<<g_big, blk, GEMM_SMEM>>>(t1h, t1l, wCl, cl_b, D2, D2, M,
        t2h, t2l, nullptr, nullptr, nullptr, nullptr, nullptr, nullptr, nullptr, nullptr);
    // 5) cb[m]
    bc2<<<M / 128, 256, BC_SMEM>>>(t2h, t2l, fc2_w, fc2_b, fc3_w, fc3_b, cb, M);
    // 6) t0 = x_ssm * x_res (s6 epilogue; xc = t2, xr = t3)   <- ncu capture lands here
    mm_h<2, 0><<<g_big, blk, GEMM_SMEM>>>(t2h, t2l, wF1, fc1_b, D2, D2, M,
        t0h, t0l, nullptr, nullptr, nullptr, t2h, t2l, t3h, t3l, cb);
    // 7) out = conv(t0, out) -> fp32 d_out
    mm_h<0, 1><<<g_out, blk, GEMM_SMEM>>>(t0h, t0l, wOut, out_b, D2, D1, M,
        nullptr, nullptr, (float*)d_out, nullptr, nullptr, nullptr, nullptr, nullptr, nullptr, nullptr);
}